// round 14
// baseline (speedup 1.0000x reference)
#include <cuda_runtime.h>
#include <cuda_bf16.h>
#include <math.h>
#include <cstdint>

#define LNUM 4
#define DDIM 512
#define HDIM 512
#define BSZ  32
#define TSTEPS 2048
#define EPS 1e-5f

// ---------------- device scratch -------------------------------------------
__device__ float g_A[(size_t)LNUM * TSTEPS * HDIM * BSZ];   // LN(zi): [l][t][h][b]
__device__ float g_h[LNUM * HDIM * BSZ];                    // final h (fp32, [l][h][b])
__device__ float g_part[2 * LNUM * 32 * 2 * BSZ];           // [p][l][cta][S/Q][b]
__device__ __align__(128) unsigned g_hflag[LNUM * 32];
__device__ __align__(128) unsigned g_pflag[LNUM * 32];
// split-bf16 operands
__device__ __nv_bfloat16 g_Xhi[(size_t)TSTEPS * BSZ * DDIM]; // [n=t*32+b][d]
__device__ __nv_bfloat16 g_Xlo[(size_t)TSTEPS * BSZ * DDIM];
__device__ __nv_bfloat16 g_Whi[(size_t)LNUM * HDIM * DDIM];
__device__ __nv_bfloat16 g_Wlo[(size_t)LNUM * HDIM * DDIM];
__device__ __nv_bfloat16 g_WOhi[(size_t)DDIM * HDIM];
__device__ __nv_bfloat16 g_WOlo[(size_t)DDIM * HDIM];
// split h state, double-buffered by parity: [p][l][b][k]
__device__ __nv_bfloat16 g_hhi[2 * LNUM * BSZ * HDIM];
__device__ __nv_bfloat16 g_hlo[2 * LNUM * BSZ * HDIM];
// split layer-3 h: [n=t*32+b][k=h]
__device__ __nv_bfloat16 g_H3hi[(size_t)TSTEPS * BSZ * HDIM];
__device__ __nv_bfloat16 g_H3lo[(size_t)TSTEPS * BSZ * HDIM];

// ---------------- primitives ------------------------------------------------
__device__ __forceinline__ unsigned ld_acq(const unsigned* p) {
    unsigned v;
    asm volatile("ld.acquire.gpu.global.u32 %0, [%1];" : "=r"(v) : "l"(p) : "memory");
    return v;
}
__device__ __forceinline__ void red_release_add1(unsigned* p) {
    asm volatile("red.release.gpu.global.add.u32 [%0], 1;" :: "l"(p) : "memory");
}
__device__ __forceinline__ void cpa16(unsigned dst, const void* src) {
    asm volatile("cp.async.cg.shared.global [%0], [%1], 16;" :: "r"(dst), "l"(src) : "memory");
}
#define CP_COMMIT() asm volatile("cp.async.commit_group;" ::: "memory")
#define CP_WAIT(N)  asm volatile("cp.async.wait_group %0;" :: "n"(N) : "memory")

__device__ __forceinline__ void poll8(const unsigned* line, int grp, unsigned tgt) {
    const unsigned* f = line + grp * 8 + (threadIdx.x & 7);
    while (!__all_sync(0xffffffffu, ld_acq(f) >= tgt)) {}
}
__device__ __forceinline__ void poll32(const unsigned* line, unsigned tgt) {
    const unsigned* f = line + (threadIdx.x & 31);
    while (!__all_sync(0xffffffffu, ld_acq(f) >= tgt)) {}
}

// warp-level bf16 MMA (sm_80+, arch-unconditional PTX)
#define MMA16816(d, a, b) \
    asm volatile("mma.sync.aligned.m16n8k16.row.col.f32.bf16.bf16.f32 " \
        "{%0,%1,%2,%3}, {%4,%5,%6,%7}, {%8,%9}, {%0,%1,%2,%3};" \
        : "+f"((d)[0]), "+f"((d)[1]), "+f"((d)[2]), "+f"((d)[3]) \
        : "r"((a)[0]), "r"((a)[1]), "r"((a)[2]), "r"((a)[3]), \
          "r"((b)[0]), "r"((b)[1]))

__device__ __forceinline__ unsigned short bfbits(__nv_bfloat16 h) {
    return __bfloat16_as_ushort(h);
}

// ---------------- init: reset per launch (graph replays!) -------------------
__global__ void k_init() {
    int idx = blockIdx.x * blockDim.x + threadIdx.x;
    if (idx < LNUM * 32) { g_hflag[idx] = 0u; g_pflag[idx] = 0u; }
    unsigned* hh = (unsigned*)g_hhi;
    unsigned* hl = (unsigned*)g_hlo;
    for (int i = idx; i < 2 * LNUM * BSZ * HDIM / 2; i += gridDim.x * blockDim.x) {
        hh[i] = 0u; hl[i] = 0u;
    }
}

// ---------------- split conversions -----------------------------------------
__global__ void k_cvt_split(const float* __restrict__ W, __nv_bfloat16* dhi,
                            __nv_bfloat16* dlo, int n4) {
    int i4 = blockIdx.x * 256 + threadIdx.x;
    if (i4 >= n4) return;
    size_t e = (size_t)i4 * 4;
    float4 v = *(const float4*)(W + e);
    float vv[4] = {v.x, v.y, v.z, v.w};
    __nv_bfloat16 h[4], lo[4];
#pragma unroll
    for (int j = 0; j < 4; j++) {
        h[j]  = __float2bfloat16(vv[j]);
        lo[j] = __float2bfloat16(vv[j] - __bfloat162float(h[j]));
    }
    __nv_bfloat162* dh = (__nv_bfloat162*)(dhi + e);
    __nv_bfloat162* dl = (__nv_bfloat162*)(dlo + e);
    __nv_bfloat162 p;
    p.x = h[0];  p.y = h[1];  dh[0] = p;
    p.x = h[2];  p.y = h[3];  dh[1] = p;
    p.x = lo[0]; p.y = lo[1]; dl[0] = p;
    p.x = lo[2]; p.y = lo[3]; dl[1] = p;
}

__global__ void k_cvt_x(const float* __restrict__ x) {
    size_t e = ((size_t)blockIdx.x * 256 + threadIdx.x) * 4;
    if (e >= (size_t)TSTEPS * BSZ * DDIM) return;
    int n = (int)(e >> 9), d = (int)(e & 511);
    int t = n >> 5, b = n & 31;
    float4 v = *(const float4*)(x + ((size_t)b * TSTEPS + t) * DDIM + d);
    float vv[4] = {v.x, v.y, v.z, v.w};
    __nv_bfloat16 h[4], lo[4];
#pragma unroll
    for (int j = 0; j < 4; j++) {
        h[j]  = __float2bfloat16(vv[j]);
        lo[j] = __float2bfloat16(vv[j] - __bfloat162float(h[j]));
    }
    __nv_bfloat162* dh = (__nv_bfloat162*)(g_Xhi + e);
    __nv_bfloat162* dl = (__nv_bfloat162*)(g_Xlo + e);
    __nv_bfloat162 p;
    p.x = h[0];  p.y = h[1];  dh[0] = p;
    p.x = h[2];  p.y = h[3];  dh[1] = p;
    p.x = lo[0]; p.y = lo[1]; dl[0] = p;
    p.x = lo[2]; p.y = lo[3]; dl[1] = p;
}

// ---------------- phase 1 (HMMA): Zi = W_ih @ X^T + b_ih --------------------
#define ZI_STAGE  73728                 // 4 * 128*72*2 bytes
#define ZI_SMEM   (2 * ZI_STAGE)

__global__ __launch_bounds__(512) void k_gemm_zi_mma(const float* __restrict__ bih) {
    extern __shared__ char smem[];
    const unsigned sb = (unsigned)__cvta_generic_to_shared(smem);
    const int tid = threadIdx.x;
    const int lane = tid & 31;
    const int w = tid >> 5;
    const int wm = w >> 2, wn = w & 3;
    const int l  = blockIdx.x >> 2;
    const int h0 = (blockIdx.x & 3) * 128;
    const int n0 = blockIdx.y * 128;

    const __nv_bfloat16* gAhi = g_Whi + ((size_t)l * HDIM + h0) * DDIM;
    const __nv_bfloat16* gAlo = g_Wlo + ((size_t)l * HDIM + h0) * DDIM;
    const __nv_bfloat16* gBhi = g_Xhi + (size_t)n0 * DDIM;
    const __nv_bfloat16* gBlo = g_Xlo + (size_t)n0 * DDIM;

    auto issue = [&](int c) {
        const unsigned stg = sb + (unsigned)(c & 1) * ZI_STAGE;
        const __nv_bfloat16* srcs[4] = {gAhi, gAlo, gBhi, gBlo};
#pragma unroll
        for (int op = 0; op < 4; op++) {
            const __nv_bfloat16* src = srcs[op] + c * 64;
            unsigned dst = stg + (unsigned)op * 18432u;
#pragma unroll
            for (int j = 0; j < 2; j++) {
                int idx = tid + j * 512;
                int r = idx >> 3, seg = idx & 7;
                cpa16(dst + (unsigned)r * 144u + (unsigned)seg * 16u,
                      src + (size_t)r * DDIM + seg * 8);
            }
        }
        CP_COMMIT();
    };

    float acc[2][4][4];
#pragma unroll
    for (int mt = 0; mt < 2; mt++)
#pragma unroll
        for (int nt = 0; nt < 4; nt++)
#pragma unroll
            for (int r = 0; r < 4; r++) acc[mt][nt][r] = 0.0f;

    issue(0); issue(1);

    for (int c = 0; c < 8; c++) {
        if (c == 7) { CP_WAIT(0); } else { CP_WAIT(1); }
        __syncthreads();

        const __nv_bfloat16* sAhi = (const __nv_bfloat16*)(smem + (c & 1) * ZI_STAGE);
        const __nv_bfloat16* sAlo = sAhi + 9216;
        const __nv_bfloat16* sBhi = sAhi + 18432;
        const __nv_bfloat16* sBlo = sAhi + 27648;

#pragma unroll
        for (int ks = 0; ks < 4; ks++) {
            const int kc = ks * 16 + (lane & 3) * 2;
            uint32_t ahi[2][4], alo[2][4];
#pragma unroll
            for (int mt = 0; mt < 2; mt++) {
                int base = (wm * 32 + mt * 16 + (lane >> 2)) * 72 + kc;
                ahi[mt][0] = *(const uint32_t*)(sAhi + base);
                ahi[mt][1] = *(const uint32_t*)(sAhi + base + 8 * 72);
                ahi[mt][2] = *(const uint32_t*)(sAhi + base + 8);
                ahi[mt][3] = *(const uint32_t*)(sAhi + base + 8 * 72 + 8);
                alo[mt][0] = *(const uint32_t*)(sAlo + base);
                alo[mt][1] = *(const uint32_t*)(sAlo + base + 8 * 72);
                alo[mt][2] = *(const uint32_t*)(sAlo + base + 8);
                alo[mt][3] = *(const uint32_t*)(sAlo + base + 8 * 72 + 8);
            }
            uint32_t bhi[4][2], blo[4][2];
#pragma unroll
            for (int nt = 0; nt < 4; nt++) {
                int base = (wn * 32 + nt * 8 + (lane >> 2)) * 72 + kc;
                bhi[nt][0] = *(const uint32_t*)(sBhi + base);
                bhi[nt][1] = *(const uint32_t*)(sBhi + base + 8);
                blo[nt][0] = *(const uint32_t*)(sBlo + base);
                blo[nt][1] = *(const uint32_t*)(sBlo + base + 8);
            }
#pragma unroll
            for (int mt = 0; mt < 2; mt++)
#pragma unroll
                for (int nt = 0; nt < 4; nt++) {
                    MMA16816(acc[mt][nt], ahi[mt], bhi[nt]);
                    MMA16816(acc[mt][nt], ahi[mt], blo[nt]);
                    MMA16816(acc[mt][nt], alo[mt], bhi[nt]);
                }
        }
        if (c < 6) { __syncthreads(); issue(c + 2); }
    }

    __syncthreads();
    float* s_out = (float*)smem;
#pragma unroll
    for (int mt = 0; mt < 2; mt++)
#pragma unroll
        for (int nt = 0; nt < 4; nt++) {
            int hr = wm * 32 + mt * 16 + (lane >> 2);
            int nc = wn * 32 + nt * 8 + (lane & 3) * 2;
            s_out[hr * 132 + nc]           = acc[mt][nt][0];
            s_out[hr * 132 + nc + 1]       = acc[mt][nt][1];
            s_out[(hr + 8) * 132 + nc]     = acc[mt][nt][2];
            s_out[(hr + 8) * 132 + nc + 1] = acc[mt][nt][3];
        }
    __syncthreads();

    for (int i = tid; i < 4 * 128 * 32; i += 512) {
        int tg = i >> 12;
        int h  = (i >> 5) & 127;
        int b  = i & 31;
        float bi = bih[l * HDIM + h0 + h];
        int t = (n0 >> 5) + tg;
        g_A[((size_t)(l * TSTEPS + t) * HDIM + h0 + h) * BSZ + b] =
            s_out[h * 132 + tg * 32 + b] + bi;
    }
}

// ---------------- LN over h for each (l,t,b), in place on g_A ---------------
__global__ __launch_bounds__(256) void k_ln(const float* __restrict__ gih,
                                            const float* __restrict__ beih) {
    const int lt = blockIdx.x;
    const int l  = lt >> 11;
    const size_t base = (size_t)lt * HDIM * BSZ;
    const int tid = threadIdx.x;
    const int b = tid & 31, w = tid >> 5;

    float v[64];
    float s = 0.0f, q = 0.0f;
#pragma unroll
    for (int i = 0; i < 64; i++) {
        float xv = g_A[base + (size_t)(w * 64 + i) * BSZ + b];
        v[i] = xv;
        s += xv;
        q = fmaf(xv, xv, q);
    }
    __shared__ float rs[8][32], rq[8][32], mu_s[32], rstd_s[32];
    rs[w][b] = s; rq[w][b] = q;
    __syncthreads();
    if (w == 0) {
        float ss = 0.0f, qq = 0.0f;
#pragma unroll
        for (int j = 0; j < 8; j++) { ss += rs[j][b]; qq += rq[j][b]; }
        float mu = ss * (1.0f / HDIM);
        float var = qq * (1.0f / HDIM) - mu * mu;
        mu_s[b] = mu;
        rstd_s[b] = rsqrtf(var + EPS);
    }
    __syncthreads();
    float mu = mu_s[b], rstd = rstd_s[b];
#pragma unroll
    for (int i = 0; i < 64; i++) {
        int h = w * 64 + i;
        g_A[base + (size_t)h * BSZ + b] =
            (v[i] - mu) * rstd * gih[l * HDIM + h] + beih[l * HDIM + h];
    }
}

// ---------------- phase 2: dual-layer interleaved HMMA recurrence -----------
// 64 CTAs; CTA (p,cl) serves rows [16cl,16cl+16) of layers 2p and 2p+1.
// SMEM: W (4x16640) | H (4x33280) | red 16896 | red2 2048 | stat 768 = 219392 B
#define SMEM_RECUR2 219392

__global__ void __launch_bounds__(256, 1)
k_recur2(const float* __restrict__ Whh, const float* __restrict__ bhh,
         const float* __restrict__ ghh, const float* __restrict__ behh) {
    extern __shared__ char smc[];
    __nv_bfloat16* WhiA = (__nv_bfloat16*)smc;        // [16][520]
    __nv_bfloat16* WloA = WhiA + 16 * 520;
    __nv_bfloat16* WhiB = WloA + 16 * 520;
    __nv_bfloat16* WloB = WhiB + 16 * 520;
    __nv_bfloat16* HhiA = WloB + 16 * 520;            // [32 b][520 k]
    __nv_bfloat16* HloA = HhiA + 32 * 520;
    __nv_bfloat16* HhiB = HloA + 32 * 520;
    __nv_bfloat16* HloB = HhiB + 32 * 520;
    float* red  = (float*)(HloB + 32 * 520);          // [8 w][16 r][33]
    float* red2 = red + 8 * 16 * 33;                  // [8 w][2][32]
    float* stat = red2 + 512;                         // 192 floats

    const int cta = blockIdx.x;          // 0..63
    const int pr  = cta >> 5;
    const int cl  = cta & 31;
    const int r0  = cl * 16;
    const int lA  = pr * 2, lB = pr * 2 + 1;
    const int tid = threadIdx.x;
    const int w   = tid >> 5;
    const int lane = tid & 31;
    const int b   = lane;

    // stationary W rows for both layers: fp32 -> split bf16 [r][k]
    {
        const float* WlA = Whh + (size_t)lA * HDIM * HDIM + (size_t)r0 * HDIM;
        const float* WlB = Whh + (size_t)lB * HDIM * HDIM + (size_t)r0 * HDIM;
        for (int idx = tid; idx < 16 * 512; idx += 256) {
            int r = idx >> 9, k = idx & 511;
            float vA = WlA[r * 512 + k];
            __nv_bfloat16 hiA = __float2bfloat16(vA);
            WhiA[r * 520 + k] = hiA;
            WloA[r * 520 + k] = __float2bfloat16(vA - __bfloat162float(hiA));
            float vB = WlB[r * 512 + k];
            __nv_bfloat16 hiB = __float2bfloat16(vB);
            WhiB[r * 520 + k] = hiB;
            WloB[r * 520 + k] = __float2bfloat16(vB - __bfloat162float(hiB));
        }
    }

    // thread (w,b) owns rows r0+2w, r0+2w+1 in each layer
    const float bhA0 = bhh[lA * HDIM + r0 + 2 * w],  bhA1 = bhh[lA * HDIM + r0 + 2 * w + 1];
    const float ghA0 = ghh[lA * HDIM + r0 + 2 * w],  ghA1 = ghh[lA * HDIM + r0 + 2 * w + 1];
    const float beA0 = behh[lA * HDIM + r0 + 2 * w], beA1 = behh[lA * HDIM + r0 + 2 * w + 1];
    const float bhB0 = bhh[lB * HDIM + r0 + 2 * w],  bhB1 = bhh[lB * HDIM + r0 + 2 * w + 1];
    const float ghB0 = ghh[lB * HDIM + r0 + 2 * w],  ghB1 = ghh[lB * HDIM + r0 + 2 * w + 1];
    const float beB0 = behh[lB * HDIM + r0 + 2 * w], beB1 = behh[lB * HDIM + r0 + 2 * w + 1];

    const unsigned* hlineA = g_hflag + lA * 32;
    const unsigned* hlineB = g_hflag + lB * 32;
    const unsigned* plineA = g_pflag + lA * 32;
    const unsigned* plineB = g_pflag + lB * 32;
    unsigned* my_hflagA = g_hflag + lA * 32 + cl;
    unsigned* my_hflagB = g_hflag + lB * 32 + cl;
    unsigned* my_pflagA = g_pflag + lA * 32 + cl;
    unsigned* my_pflagB = g_pflag + lB * 32 + cl;

    const unsigned HhiA_b = (unsigned)__cvta_generic_to_shared(HhiA);
    const unsigned HloA_b = (unsigned)__cvta_generic_to_shared(HloA);
    const unsigned HhiB_b = (unsigned)__cvta_generic_to_shared(HhiB);
    const unsigned HloB_b = (unsigned)__cvta_generic_to_shared(HloB);

    // ---- lambdas ----
    auto issue_q = [&](const __nv_bfloat16* hin_hi, const __nv_bfloat16* hin_lo,
                       unsigned Hhi_b, unsigned Hlo_b, int Q) {
#pragma unroll
        for (int j = 0; j < 4; j++) {
            int t4 = j * 256 + tid;
            int slab = t4 >> 9;
            int row = (t4 >> 4) & 31;
            int cch = t4 & 15;
            unsigned dst = (slab ? Hlo_b : Hhi_b)
                         + (unsigned)row * 1040u + (unsigned)Q * 256u + (unsigned)cch * 16u;
            const __nv_bfloat16* src = (slab ? hin_lo : hin_hi)
                                     + (size_t)row * 512 + Q * 128 + cch * 8;
            cpa16(dst, src);
        }
        CP_COMMIT();
    };

    auto mv = [&](const __nv_bfloat16* Whi_s, const __nv_bfloat16* Wlo_s,
                  const __nv_bfloat16* Hhi_s, const __nv_bfloat16* Hlo_s,
                  float (&acc)[4][4], int Q) {
        const int kc = Q * 128 + w * 16 + (lane & 3) * 2;
        const int r_l = lane >> 2;
        int abase = r_l * 520 + kc;
        uint32_t Ahi[4], Alo[4];
        Ahi[0] = *(const uint32_t*)(Whi_s + abase);
        Ahi[1] = *(const uint32_t*)(Whi_s + abase + 8 * 520);
        Ahi[2] = *(const uint32_t*)(Whi_s + abase + 8);
        Ahi[3] = *(const uint32_t*)(Whi_s + abase + 8 * 520 + 8);
        Alo[0] = *(const uint32_t*)(Wlo_s + abase);
        Alo[1] = *(const uint32_t*)(Wlo_s + abase + 8 * 520);
        Alo[2] = *(const uint32_t*)(Wlo_s + abase + 8);
        Alo[3] = *(const uint32_t*)(Wlo_s + abase + 8 * 520 + 8);
#pragma unroll
        for (int nf = 0; nf < 4; nf++) {
            int bbase = (nf * 8 + r_l) * 520 + kc;
            uint32_t Bhi[2], Blo[2];
            Bhi[0] = *(const uint32_t*)(Hhi_s + bbase);
            Bhi[1] = *(const uint32_t*)(Hhi_s + bbase + 8);
            Blo[0] = *(const uint32_t*)(Hlo_s + bbase);
            Blo[1] = *(const uint32_t*)(Hlo_s + bbase + 8);
            MMA16816(acc[nf], Ahi, Bhi);
            MMA16816(acc[nf], Ahi, Blo);
            MMA16816(acc[nf], Alo, Bhi);
        }
    };

    auto finish_z = [&](float (&acc)[4][4], float bh0, float bh1, float* pbL,
                        unsigned* my_pflag, float& z0, float& z1) {
        {
            const int rr = lane >> 2;
            const int bc = (lane & 3) * 2;
#pragma unroll
            for (int nf = 0; nf < 4; nf++) {
                int bb = nf * 8 + bc;
                red[(w * 16 + rr) * 33 + bb]         = acc[nf][0];
                red[(w * 16 + rr) * 33 + bb + 1]     = acc[nf][1];
                red[(w * 16 + rr + 8) * 33 + bb]     = acc[nf][2];
                red[(w * 16 + rr + 8) * 33 + bb + 1] = acc[nf][3];
            }
        }
        __syncthreads();
        z0 = bh0; z1 = bh1;
#pragma unroll
        for (int wp = 0; wp < 8; wp++) {
            z0 += red[(wp * 16 + 2 * w) * 33 + b];
            z1 += red[(wp * 16 + 2 * w + 1) * 33 + b];
        }
        red2[(w * 2 + 0) * 32 + b] = z0 + z1;
        red2[(w * 2 + 1) * 32 + b] = fmaf(z0, z0, z1 * z1);
        __syncthreads();
        if (w == 0) {
            float S = 0.f, Q = 0.f;
#pragma unroll
            for (int j = 0; j < 8; j++) { S += red2[(j * 2) * 32 + b]; Q += red2[(j * 2 + 1) * 32 + b]; }
            pbL[cl * 64 + b]      = S;
            pbL[cl * 64 + 32 + b] = Q;
            __syncwarp();
            if (b == 0) red_release_add1(my_pflag);
        }
    };

    auto stats_h = [&](float z0, float z1, float a0, float a1,
                       float gh0, float gh1, float be0, float be1,
                       const unsigned* pline, unsigned* my_hflag, const float* pbL,
                       unsigned* houth, unsigned* houtl, int ll, int s) {
        if (w == 0) {
            poll32(pline, (unsigned)(s + 1));
            float S2 = 0.f, Q2 = 0.f;
#pragma unroll 4
            for (int cc = 0; cc < 16; cc++) {
                S2 += __ldcg(pbL + cc * 64 + b);
                Q2 += __ldcg(pbL + cc * 64 + 32 + b);
            }
            stat[64 + b] = S2; stat[96 + b] = Q2;
        } else if (w == 1) {
            poll32(pline, (unsigned)(s + 1));
            float S2 = 0.f, Q2 = 0.f;
#pragma unroll 4
            for (int cc = 16; cc < 32; cc++) {
                S2 += __ldcg(pbL + cc * 64 + b);
                Q2 += __ldcg(pbL + cc * 64 + 32 + b);
            }
            stat[128 + b] = S2; stat[160 + b] = Q2;
        }
        if (w < 2) {
            asm volatile("bar.sync 1, 64;" ::: "memory");
            if (w == 0) {
                float S = stat[64 + b] + stat[128 + b];
                float Q = stat[96 + b] + stat[160 + b];
                float mu = S * (1.0f / HDIM);
                float var = Q * (1.0f / HDIM) - mu * mu;
                stat[b] = mu;
                stat[32 + b] = rsqrtf(var + EPS);
            }
        }
        __syncthreads();
        float mu = stat[b], rstd = stat[32 + b];
        float h0 = tanhf(a0 + (z0 - mu) * rstd * gh0 + be0);
        float h1 = tanhf(a1 + (z1 - mu) * rstd * gh1 + be1);
        __nv_bfloat16 h0hi = __float2bfloat16(h0);
        __nv_bfloat16 h1hi = __float2bfloat16(h1);
        __nv_bfloat16 h0lo = __float2bfloat16(h0 - __bfloat162float(h0hi));
        __nv_bfloat16 h1lo = __float2bfloat16(h1 - __bfloat162float(h1hi));
        unsigned hipack = (unsigned)bfbits(h0hi) | ((unsigned)bfbits(h1hi) << 16);
        unsigned lopack = (unsigned)bfbits(h0lo) | ((unsigned)bfbits(h1lo) << 16);
        int u32idx = b * 256 + cl * 8 + w;
        houth[u32idx] = hipack;
        houtl[u32idx] = lopack;
        if (ll == 3) {
            int h3idx = (s * 32 + b) * 256 + cl * 8 + w;
            ((unsigned*)g_H3hi)[h3idx] = hipack;
            ((unsigned*)g_H3lo)[h3idx] = lopack;
        }
        if (s == TSTEPS - 1) {
            g_h[(size_t)ll * (HDIM * BSZ) + (size_t)(r0 + 2 * w) * BSZ + b]     = h0;
            g_h[(size_t)ll * (HDIM * BSZ) + (size_t)(r0 + 2 * w + 1) * BSZ + b] = h1;
        }
        __syncthreads();
        if (tid == 0) red_release_add1(my_hflag);
    };

    __syncthreads();

    for (int s = 0; s < TSTEPS; s++) {
        const __nv_bfloat16* hinhA = g_hhi + (size_t)((s & 1) * LNUM + lA) * (BSZ * HDIM);
        const __nv_bfloat16* hinlA = g_hlo + (size_t)((s & 1) * LNUM + lA) * (BSZ * HDIM);
        const __nv_bfloat16* hinhB = g_hhi + (size_t)((s & 1) * LNUM + lB) * (BSZ * HDIM);
        const __nv_bfloat16* hinlB = g_hlo + (size_t)((s & 1) * LNUM + lB) * (BSZ * HDIM);
        unsigned* houthA = (unsigned*)(g_hhi + (size_t)(((s + 1) & 1) * LNUM + lA) * (BSZ * HDIM));
        unsigned* houtlA = (unsigned*)(g_hlo + (size_t)(((s + 1) & 1) * LNUM + lA) * (BSZ * HDIM));
        unsigned* houthB = (unsigned*)(g_hhi + (size_t)(((s + 1) & 1) * LNUM + lB) * (BSZ * HDIM));
        unsigned* houtlB = (unsigned*)(g_hlo + (size_t)(((s + 1) & 1) * LNUM + lB) * (BSZ * HDIM));
        float* pbA = g_part + (size_t)((s & 1) * LNUM + lA) * (32 * 2 * BSZ);
        float* pbB = g_part + (size_t)((s & 1) * LNUM + lB) * (32 * 2 * BSZ);

        // a_t prefetch for both layers (own 2 rows each)
        const float* aAp = g_A + ((size_t)lA * TSTEPS + s) * HDIM * BSZ;
        const float* aBp = g_A + ((size_t)lB * TSTEPS + s) * HDIM * BSZ;
        float aA0 = __ldcs(aAp + (size_t)(r0 + 2 * w) * BSZ + b);
        float aA1 = __ldcs(aAp + (size_t)(r0 + 2 * w + 1) * BSZ + b);
        float aB0 = __ldcs(aBp + (size_t)(r0 + 2 * w) * BSZ + b);
        float aB1 = __ldcs(aBp + (size_t)(r0 + 2 * w + 1) * BSZ + b);

        float acc[4][4];
#pragma unroll
        for (int nf = 0; nf < 4; nf++)
#pragma unroll
            for (int r = 0; r < 4; r++) acc[nf][r] = 0.0f;

        // ---- layer A slab: 4 quarter polls + issues (groups 1-4) ----
        if (w == 0) poll8(hlineA, 0, (unsigned)s);
        __syncthreads();
        issue_q(hinhA, hinlA, HhiA_b, HloA_b, 0);
        if (w == 0) poll8(hlineA, 1, (unsigned)s);
        __syncthreads();
        issue_q(hinhA, hinlA, HhiA_b, HloA_b, 1);
        if (w == 0) poll8(hlineA, 2, (unsigned)s);
        __syncthreads();
        issue_q(hinhA, hinlA, HhiA_b, HloA_b, 2);
        if (w == 0) poll8(hlineA, 3, (unsigned)s);
        __syncthreads();
        issue_q(hinhA, hinlA, HhiA_b, HloA_b, 3);

        // ---- mvA quarters interleaved with layer-B polls/issues (groups 5-8) ----
        CP_WAIT(3); __syncthreads();
        mv(WhiA, WloA, HhiA, HloA, acc, 0);
        if (w == 0) poll8(hlineB, 0, (unsigned)s);
        __syncthreads();
        issue_q(hinhB, hinlB, HhiB_b, HloB_b, 0);

        CP_WAIT(3); __syncthreads();
        mv(WhiA, WloA, HhiA, HloA, acc, 1);
        if (w == 0) poll8(hlineB, 1, (unsigned)s);
        __syncthreads();
        issue_q(hinhB, hinlB, HhiB_b, HloB_b, 1);

        CP_WAIT(3); __syncthreads();
        mv(WhiA, WloA, HhiA, HloA, acc, 2);
        if (w == 0) poll8(hlineB, 2, (unsigned)s);
        __syncthreads();
        issue_q(hinhB, hinlB, HhiB_b, HloB_b, 2);

        CP_WAIT(3); __syncthreads();
        mv(WhiA, WloA, HhiA, HloA, acc, 3);
        if (w == 0) poll8(hlineB, 3, (unsigned)s);
        __syncthreads();
        issue_q(hinhB, hinlB, HhiB_b, HloB_b, 3);

        // ---- A epilogue: z + partials publish ----
        float zA0, zA1;
        finish_z(acc, bhA0, bhA1, pbA, my_pflagA, zA0, zA1);

        // ---- B matvec ----
        CP_WAIT(0); __syncthreads();
#pragma unroll
        for (int nf = 0; nf < 4; nf++)
#pragma unroll
            for (int r = 0; r < 4; r++) acc[nf][r] = 0.0f;
        mv(WhiB, WloB, HhiB, HloB, acc, 0);
        mv(WhiB, WloB, HhiB, HloB, acc, 1);
        mv(WhiB, WloB, HhiB, HloB, acc, 2);
        mv(WhiB, WloB, HhiB, HloB, acc, 3);

        float zB0, zB1;
        finish_z(acc, bhB0, bhB1, pbB, my_pflagB, zB0, zB1);

        // ---- stats + h publish: A then B ----
        stats_h(zA0, zA1, aA0, aA1, ghA0, ghA1, beA0, beA1,
                plineA, my_hflagA, pbA, houthA, houtlA, lA, s);
        stats_h(zB0, zB1, aB0, aB1, ghB0, ghB1, beB0, beB1,
                plineB, my_hflagB, pbB, houthB, houtlB, lB, s);
    }
}

// ---------------- phase 3 (HMMA): out = h3 @ W_ho^T + b_ho + x --------------
__global__ __launch_bounds__(512) void k_gemm_out_mma(const float* __restrict__ bho,
                                                      const float* __restrict__ x,
                                                      float* __restrict__ out) {
    extern __shared__ char smem[];
    const unsigned sb = (unsigned)__cvta_generic_to_shared(smem);
    const int tid = threadIdx.x;
    const int lane = tid & 31;
    const int w = tid >> 5;
    const int wm = w >> 2, wn = w & 3;
    const int d0 = blockIdx.x * 128;
    const int n0 = blockIdx.y * 128;

    const __nv_bfloat16* gAhi = g_WOhi + (size_t)d0 * HDIM;
    const __nv_bfloat16* gAlo = g_WOlo + (size_t)d0 * HDIM;
    const __nv_bfloat16* gBhi = g_H3hi + (size_t)n0 * HDIM;
    const __nv_bfloat16* gBlo = g_H3lo + (size_t)n0 * HDIM;

    auto issue = [&](int c) {
        const unsigned stg = sb + (unsigned)(c & 1) * ZI_STAGE;
        const __nv_bfloat16* srcs[4] = {gAhi, gAlo, gBhi, gBlo};
#pragma unroll
        for (int op = 0; op < 4; op++) {
            const __nv_bfloat16* src = srcs[op] + c * 64;
            unsigned dst = stg + (unsigned)op * 18432u;
#pragma unroll
            for (int j = 0; j < 2; j++) {
                int idx = tid + j * 512;
                int r = idx >> 3, seg = idx & 7;
                cpa16(dst + (unsigned)r * 144u + (unsigned)seg * 16u,
                      src + (size_t)r * HDIM + seg * 8);
            }
        }
        CP_COMMIT();
    };

    float acc[2][4][4];
#pragma unroll
    for (int mt = 0; mt < 2; mt++)
#pragma unroll
        for (int nt = 0; nt < 4; nt++)
#pragma unroll
            for (int r = 0; r < 4; r++) acc[mt][nt][r] = 0.0f;

    issue(0); issue(1);

    for (int c = 0; c < 8; c++) {
        if (c == 7) { CP_WAIT(0); } else { CP_WAIT(1); }
        __syncthreads();

        const __nv_bfloat16* sAhi = (const __nv_bfloat16*)(smem + (c & 1) * ZI_STAGE);
        const __nv_bfloat16* sAlo = sAhi + 9216;
        const __nv_bfloat16* sBhi = sAhi + 18432;
        const __nv_bfloat16* sBlo = sAhi + 27648;

#pragma unroll
        for (int ks = 0; ks < 4; ks++) {
            const int kc = ks * 16 + (lane & 3) * 2;
            uint32_t ahi[2][4], alo[2][4];
#pragma unroll
            for (int mt = 0; mt < 2; mt++) {
                int base = (wm * 32 + mt * 16 + (lane >> 2)) * 72 + kc;
                ahi[mt][0] = *(const uint32_t*)(sAhi + base);
                ahi[mt][1] = *(const uint32_t*)(sAhi + base + 8 * 72);
                ahi[mt][2] = *(const uint32_t*)(sAhi + base + 8);
                ahi[mt][3] = *(const uint32_t*)(sAhi + base + 8 * 72 + 8);
                alo[mt][0] = *(const uint32_t*)(sAlo + base);
                alo[mt][1] = *(const uint32_t*)(sAlo + base + 8 * 72);
                alo[mt][2] = *(const uint32_t*)(sAlo + base + 8);
                alo[mt][3] = *(const uint32_t*)(sAlo + base + 8 * 72 + 8);
            }
            uint32_t bhi[4][2], blo[4][2];
#pragma unroll
            for (int nt = 0; nt < 4; nt++) {
                int base = (wn * 32 + nt * 8 + (lane >> 2)) * 72 + kc;
                bhi[nt][0] = *(const uint32_t*)(sBhi + base);
                bhi[nt][1] = *(const uint32_t*)(sBhi + base + 8);
                blo[nt][0] = *(const uint32_t*)(sBlo + base);
                blo[nt][1] = *(const uint32_t*)(sBlo + base + 8);
            }
#pragma unroll
            for (int mt = 0; mt < 2; mt++)
#pragma unroll
                for (int nt = 0; nt < 4; nt++) {
                    MMA16816(acc[mt][nt], ahi[mt], bhi[nt]);
                    MMA16816(acc[mt][nt], ahi[mt], blo[nt]);
                    MMA16816(acc[mt][nt], alo[mt], bhi[nt]);
                }
        }
        if (c < 6) { __syncthreads(); issue(c + 2); }
    }

    __syncthreads();
    float* s_out = (float*)smem;
#pragma unroll
    for (int mt = 0; mt < 2; mt++)
#pragma unroll
        for (int nt = 0; nt < 4; nt++) {
            int hr = wm * 32 + mt * 16 + (lane >> 2);
            int nc = wn * 32 + nt * 8 + (lane & 3) * 2;
            s_out[nc * 132 + hr]           = acc[mt][nt][0];
            s_out[(nc + 1) * 132 + hr]     = acc[mt][nt][1];
            s_out[nc * 132 + hr + 8]       = acc[mt][nt][2];
            s_out[(nc + 1) * 132 + hr + 8] = acc[mt][nt][3];
        }
    __syncthreads();

    for (int i = tid; i < 128 * 128; i += 512) {
        int n = i >> 7;
        int dd = i & 127;
        int tg = n >> 5, bb = n & 31;
        int t = (n0 >> 5) + tg;
        int d = d0 + dd;
        size_t oidx = ((size_t)bb * TSTEPS + t) * DDIM + d;
        out[oidx] = s_out[n * 132 + dd] + bho[d] + x[oidx];
    }
}

// ---------------- h_final: [L,B,H] from g_h ([l][h][b]) ---------------------
__global__ void k_hfinal(float* __restrict__ out2) {
    int idx = blockIdx.x * 256 + threadIdx.x;
    int l = idx >> 14;
    int rem = idx & 16383;
    int bb = rem >> 9;
    int hh = rem & 511;
    out2[idx] = g_h[(size_t)l * (HDIM * BSZ) + (size_t)hh * BSZ + bb];
}

// ---------------- launch -----------------------------------------------------
extern "C" void kernel_launch(void* const* d_in, const int* in_sizes, int n_in,
                              void* d_out, int out_size) {
    const float* x    = (const float*)d_in[0];
    const float* Wih  = (const float*)d_in[1];
    const float* bih  = (const float*)d_in[2];
    const float* gih  = (const float*)d_in[3];
    const float* beih = (const float*)d_in[4];
    const float* Whh  = (const float*)d_in[5];
    const float* bhh  = (const float*)d_in[6];
    const float* ghh  = (const float*)d_in[7];
    const float* behh = (const float*)d_in[8];
    const float* Who  = (const float*)d_in[9];
    const float* bho  = (const float*)d_in[10];
    float* out = (float*)d_out;

    cudaFuncSetAttribute(k_recur2, cudaFuncAttributeMaxDynamicSharedMemorySize, SMEM_RECUR2);
    cudaFuncSetAttribute(k_gemm_zi_mma, cudaFuncAttributeMaxDynamicSharedMemorySize, ZI_SMEM);
    cudaFuncSetAttribute(k_gemm_out_mma, cudaFuncAttributeMaxDynamicSharedMemorySize, ZI_SMEM);

    k_init<<<64, 256>>>();
    {   // W_ih split
        __nv_bfloat16 *dhi, *dlo;
        cudaGetSymbolAddress((void**)&dhi, g_Whi);
        cudaGetSymbolAddress((void**)&dlo, g_Wlo);
        int n4 = LNUM * HDIM * DDIM / 4;
        k_cvt_split<<<(n4 + 255) / 256, 256>>>(Wih, dhi, dlo, n4);
    }
    {   // W_ho split
        __nv_bfloat16 *dhi, *dlo;
        cudaGetSymbolAddress((void**)&dhi, g_WOhi);
        cudaGetSymbolAddress((void**)&dlo, g_WOlo);
        int n4 = DDIM * HDIM / 4;
        k_cvt_split<<<(n4 + 255) / 256, 256>>>(Who, dhi, dlo, n4);
    }
    k_cvt_x<<<(TSTEPS * BSZ * DDIM / 4 + 255) / 256, 256>>>(x);
    k_gemm_zi_mma<<<dim3(16, 512), 512, ZI_SMEM>>>(bih);
    k_ln<<<LNUM * TSTEPS, 256>>>(gih, beih);
    k_recur2<<<64, 256, SMEM_RECUR2>>>(Whh, bhh, ghh, behh);
    k_gemm_out_mma<<<dim3(4, 512), 512, ZI_SMEM>>>(bho, x, out);
    k_hfinal<<<256, 256>>>(out + (size_t)BSZ * TSTEPS * DDIM);
}

// round 15
// speedup vs baseline: 1.5515x; 1.5515x over previous
#include <cuda_runtime.h>
#include <cuda_bf16.h>
#include <math.h>
#include <cstdint>

#define LNUM 4
#define DDIM 512
#define HDIM 512
#define BSZ  32
#define TSTEPS 2048
#define EPS 1e-5f

// ---------------- device scratch -------------------------------------------
__device__ float g_A[(size_t)LNUM * TSTEPS * HDIM * BSZ];   // LN(zi): [l][t][h][b]
__device__ float g_h[LNUM * HDIM * BSZ];                    // final h (fp32, [l][h][b])
__device__ float g_part[2 * LNUM * 32 * 2 * BSZ];           // [p][l][cta][S/Q][b]
__device__ __align__(128) unsigned g_hflag[LNUM * 32];
__device__ __align__(128) unsigned g_pflag[LNUM * 32];
// split-bf16 operands
__device__ __nv_bfloat16 g_Xhi[(size_t)TSTEPS * BSZ * DDIM]; // [n=t*32+b][d]
__device__ __nv_bfloat16 g_Xlo[(size_t)TSTEPS * BSZ * DDIM];
__device__ __nv_bfloat16 g_Whi[(size_t)LNUM * HDIM * DDIM];
__device__ __nv_bfloat16 g_Wlo[(size_t)LNUM * HDIM * DDIM];
__device__ __nv_bfloat16 g_WOhi[(size_t)DDIM * HDIM];
__device__ __nv_bfloat16 g_WOlo[(size_t)DDIM * HDIM];
// split h state, double-buffered by parity: [p][l][b][k]
__device__ __nv_bfloat16 g_hhi[2 * LNUM * BSZ * HDIM];
__device__ __nv_bfloat16 g_hlo[2 * LNUM * BSZ * HDIM];
// split layer-3 h: [n=t*32+b][k=h]
__device__ __nv_bfloat16 g_H3hi[(size_t)TSTEPS * BSZ * HDIM];
__device__ __nv_bfloat16 g_H3lo[(size_t)TSTEPS * BSZ * HDIM];

// ---------------- primitives ------------------------------------------------
__device__ __forceinline__ unsigned ld_acq(const unsigned* p) {
    unsigned v;
    asm volatile("ld.acquire.gpu.global.u32 %0, [%1];" : "=r"(v) : "l"(p) : "memory");
    return v;
}
__device__ __forceinline__ void red_release_add1(unsigned* p) {
    asm volatile("red.release.gpu.global.add.u32 [%0], 1;" :: "l"(p) : "memory");
}
__device__ __forceinline__ void cpa16(unsigned dst, const void* src) {
    asm volatile("cp.async.cg.shared.global [%0], [%1], 16;" :: "r"(dst), "l"(src) : "memory");
}
#define CP_COMMIT() asm volatile("cp.async.commit_group;" ::: "memory")
#define CP_WAIT(N)  asm volatile("cp.async.wait_group %0;" :: "n"(N) : "memory")

// poll 4 producer flags (one slab quarter), warp-wide
__device__ __forceinline__ void poll4(const unsigned* line, int grp, unsigned tgt) {
    const unsigned* f = line + grp * 4 + (threadIdx.x & 3);
    while (!__all_sync(0xffffffffu, ld_acq(f) >= tgt)) {}
}
// poll 16 flags (all layer CTAs), warp-wide
__device__ __forceinline__ void poll16f(const unsigned* line, unsigned tgt) {
    const unsigned* f = line + (threadIdx.x & 15);
    while (!__all_sync(0xffffffffu, ld_acq(f) >= tgt)) {}
}

// warp-level bf16 MMA (sm_80+, arch-unconditional PTX)
#define MMA16816(d, a, b) \
    asm volatile("mma.sync.aligned.m16n8k16.row.col.f32.bf16.bf16.f32 " \
        "{%0,%1,%2,%3}, {%4,%5,%6,%7}, {%8,%9}, {%0,%1,%2,%3};" \
        : "+f"((d)[0]), "+f"((d)[1]), "+f"((d)[2]), "+f"((d)[3]) \
        : "r"((a)[0]), "r"((a)[1]), "r"((a)[2]), "r"((a)[3]), \
          "r"((b)[0]), "r"((b)[1]))

__device__ __forceinline__ unsigned short bfbits(__nv_bfloat16 h) {
    return __bfloat16_as_ushort(h);
}

// ---------------- init: reset per launch (graph replays!) -------------------
__global__ void k_init() {
    int idx = blockIdx.x * blockDim.x + threadIdx.x;
    if (idx < LNUM * 32) { g_hflag[idx] = 0u; g_pflag[idx] = 0u; }
    unsigned* hh = (unsigned*)g_hhi;
    unsigned* hl = (unsigned*)g_hlo;
    for (int i = idx; i < 2 * LNUM * BSZ * HDIM / 2; i += gridDim.x * blockDim.x) {
        hh[i] = 0u; hl[i] = 0u;
    }
}

// ---------------- split conversions -----------------------------------------
__global__ void k_cvt_split(const float* __restrict__ W, __nv_bfloat16* dhi,
                            __nv_bfloat16* dlo, int n4) {
    int i4 = blockIdx.x * 256 + threadIdx.x;
    if (i4 >= n4) return;
    size_t e = (size_t)i4 * 4;
    float4 v = *(const float4*)(W + e);
    float vv[4] = {v.x, v.y, v.z, v.w};
    __nv_bfloat16 h[4], lo[4];
#pragma unroll
    for (int j = 0; j < 4; j++) {
        h[j]  = __float2bfloat16(vv[j]);
        lo[j] = __float2bfloat16(vv[j] - __bfloat162float(h[j]));
    }
    __nv_bfloat162* dh = (__nv_bfloat162*)(dhi + e);
    __nv_bfloat162* dl = (__nv_bfloat162*)(dlo + e);
    __nv_bfloat162 p;
    p.x = h[0];  p.y = h[1];  dh[0] = p;
    p.x = h[2];  p.y = h[3];  dh[1] = p;
    p.x = lo[0]; p.y = lo[1]; dl[0] = p;
    p.x = lo[2]; p.y = lo[3]; dl[1] = p;
}

__global__ void k_cvt_x(const float* __restrict__ x) {
    size_t e = ((size_t)blockIdx.x * 256 + threadIdx.x) * 4;
    if (e >= (size_t)TSTEPS * BSZ * DDIM) return;
    int n = (int)(e >> 9), d = (int)(e & 511);
    int t = n >> 5, b = n & 31;
    float4 v = *(const float4*)(x + ((size_t)b * TSTEPS + t) * DDIM + d);
    float vv[4] = {v.x, v.y, v.z, v.w};
    __nv_bfloat16 h[4], lo[4];
#pragma unroll
    for (int j = 0; j < 4; j++) {
        h[j]  = __float2bfloat16(vv[j]);
        lo[j] = __float2bfloat16(vv[j] - __bfloat162float(h[j]));
    }
    __nv_bfloat162* dh = (__nv_bfloat162*)(g_Xhi + e);
    __nv_bfloat162* dl = (__nv_bfloat162*)(g_Xlo + e);
    __nv_bfloat162 p;
    p.x = h[0];  p.y = h[1];  dh[0] = p;
    p.x = h[2];  p.y = h[3];  dh[1] = p;
    p.x = lo[0]; p.y = lo[1]; dl[0] = p;
    p.x = lo[2]; p.y = lo[3]; dl[1] = p;
}

// ---------------- phase 1 (HMMA): Zi = W_ih @ X^T + b_ih --------------------
#define ZI_STAGE  73728                 // 4 * 128*72*2 bytes
#define ZI_SMEM   (2 * ZI_STAGE)

__global__ __launch_bounds__(512) void k_gemm_zi_mma(const float* __restrict__ bih) {
    extern __shared__ char smem[];
    const unsigned sb = (unsigned)__cvta_generic_to_shared(smem);
    const int tid = threadIdx.x;
    const int lane = tid & 31;
    const int w = tid >> 5;
    const int wm = w >> 2, wn = w & 3;
    const int l  = blockIdx.x >> 2;
    const int h0 = (blockIdx.x & 3) * 128;
    const int n0 = blockIdx.y * 128;

    const __nv_bfloat16* gAhi = g_Whi + ((size_t)l * HDIM + h0) * DDIM;
    const __nv_bfloat16* gAlo = g_Wlo + ((size_t)l * HDIM + h0) * DDIM;
    const __nv_bfloat16* gBhi = g_Xhi + (size_t)n0 * DDIM;
    const __nv_bfloat16* gBlo = g_Xlo + (size_t)n0 * DDIM;

    auto issue = [&](int c) {
        const unsigned stg = sb + (unsigned)(c & 1) * ZI_STAGE;
        const __nv_bfloat16* srcs[4] = {gAhi, gAlo, gBhi, gBlo};
#pragma unroll
        for (int op = 0; op < 4; op++) {
            const __nv_bfloat16* src = srcs[op] + c * 64;
            unsigned dst = stg + (unsigned)op * 18432u;
#pragma unroll
            for (int j = 0; j < 2; j++) {
                int idx = tid + j * 512;
                int r = idx >> 3, seg = idx & 7;
                cpa16(dst + (unsigned)r * 144u + (unsigned)seg * 16u,
                      src + (size_t)r * DDIM + seg * 8);
            }
        }
        CP_COMMIT();
    };

    float acc[2][4][4];
#pragma unroll
    for (int mt = 0; mt < 2; mt++)
#pragma unroll
        for (int nt = 0; nt < 4; nt++)
#pragma unroll
            for (int r = 0; r < 4; r++) acc[mt][nt][r] = 0.0f;

    issue(0); issue(1);

    for (int c = 0; c < 8; c++) {
        if (c == 7) { CP_WAIT(0); } else { CP_WAIT(1); }
        __syncthreads();

        const __nv_bfloat16* sAhi = (const __nv_bfloat16*)(smem + (c & 1) * ZI_STAGE);
        const __nv_bfloat16* sAlo = sAhi + 9216;
        const __nv_bfloat16* sBhi = sAhi + 18432;
        const __nv_bfloat16* sBlo = sAhi + 27648;

#pragma unroll
        for (int ks = 0; ks < 4; ks++) {
            const int kc = ks * 16 + (lane & 3) * 2;
            uint32_t ahi[2][4], alo[2][4];
#pragma unroll
            for (int mt = 0; mt < 2; mt++) {
                int base = (wm * 32 + mt * 16 + (lane >> 2)) * 72 + kc;
                ahi[mt][0] = *(const uint32_t*)(sAhi + base);
                ahi[mt][1] = *(const uint32_t*)(sAhi + base + 8 * 72);
                ahi[mt][2] = *(const uint32_t*)(sAhi + base + 8);
                ahi[mt][3] = *(const uint32_t*)(sAhi + base + 8 * 72 + 8);
                alo[mt][0] = *(const uint32_t*)(sAlo + base);
                alo[mt][1] = *(const uint32_t*)(sAlo + base + 8 * 72);
                alo[mt][2] = *(const uint32_t*)(sAlo + base + 8);
                alo[mt][3] = *(const uint32_t*)(sAlo + base + 8 * 72 + 8);
            }
            uint32_t bhi[4][2], blo[4][2];
#pragma unroll
            for (int nt = 0; nt < 4; nt++) {
                int base = (wn * 32 + nt * 8 + (lane >> 2)) * 72 + kc;
                bhi[nt][0] = *(const uint32_t*)(sBhi + base);
                bhi[nt][1] = *(const uint32_t*)(sBhi + base + 8);
                blo[nt][0] = *(const uint32_t*)(sBlo + base);
                blo[nt][1] = *(const uint32_t*)(sBlo + base + 8);
            }
#pragma unroll
            for (int mt = 0; mt < 2; mt++)
#pragma unroll
                for (int nt = 0; nt < 4; nt++) {
                    MMA16816(acc[mt][nt], ahi[mt], bhi[nt]);
                    MMA16816(acc[mt][nt], ahi[mt], blo[nt]);
                    MMA16816(acc[mt][nt], alo[mt], bhi[nt]);
                }
        }
        if (c < 6) { __syncthreads(); issue(c + 2); }
    }

    __syncthreads();
    float* s_out = (float*)smem;
#pragma unroll
    for (int mt = 0; mt < 2; mt++)
#pragma unroll
        for (int nt = 0; nt < 4; nt++) {
            int hr = wm * 32 + mt * 16 + (lane >> 2);
            int nc = wn * 32 + nt * 8 + (lane & 3) * 2;
            s_out[hr * 132 + nc]           = acc[mt][nt][0];
            s_out[hr * 132 + nc + 1]       = acc[mt][nt][1];
            s_out[(hr + 8) * 132 + nc]     = acc[mt][nt][2];
            s_out[(hr + 8) * 132 + nc + 1] = acc[mt][nt][3];
        }
    __syncthreads();

    for (int i = tid; i < 4 * 128 * 32; i += 512) {
        int tg = i >> 12;
        int h  = (i >> 5) & 127;
        int b  = i & 31;
        float bi = bih[l * HDIM + h0 + h];
        int t = (n0 >> 5) + tg;
        g_A[((size_t)(l * TSTEPS + t) * HDIM + h0 + h) * BSZ + b] =
            s_out[h * 132 + tg * 32 + b] + bi;
    }
}

// ---------------- LN over h for each (l,t,b), in place on g_A ---------------
__global__ __launch_bounds__(256) void k_ln(const float* __restrict__ gih,
                                            const float* __restrict__ beih) {
    const int lt = blockIdx.x;
    const int l  = lt >> 11;
    const size_t base = (size_t)lt * HDIM * BSZ;
    const int tid = threadIdx.x;
    const int b = tid & 31, w = tid >> 5;

    float v[64];
    float s = 0.0f, q = 0.0f;
#pragma unroll
    for (int i = 0; i < 64; i++) {
        float xv = g_A[base + (size_t)(w * 64 + i) * BSZ + b];
        v[i] = xv;
        s += xv;
        q = fmaf(xv, xv, q);
    }
    __shared__ float rs[8][32], rq[8][32], mu_s[32], rstd_s[32];
    rs[w][b] = s; rq[w][b] = q;
    __syncthreads();
    if (w == 0) {
        float ss = 0.0f, qq = 0.0f;
#pragma unroll
        for (int j = 0; j < 8; j++) { ss += rs[j][b]; qq += rq[j][b]; }
        float mu = ss * (1.0f / HDIM);
        float var = qq * (1.0f / HDIM) - mu * mu;
        mu_s[b] = mu;
        rstd_s[b] = rsqrtf(var + EPS);
    }
    __syncthreads();
    float mu = mu_s[b], rstd = rstd_s[b];
#pragma unroll
    for (int i = 0; i < 64; i++) {
        int h = w * 64 + i;
        g_A[base + (size_t)h * BSZ + b] =
            (v[i] - mu) * rstd * gih[l * HDIM + h] + beih[l * HDIM + h];
    }
}

// ---------------- phase 2: HMMA dataflow recurrence, 16 CTAs/layer ----------
// 64 CTAs, 512 threads. CTA (l, cl<16) owns rows [32cl, 32cl+32) of layer l.
// SMEM bytes: Whi 33280 | Wlo 33280 | Hhi 33280 | Hlo 33280 | red 33792 | red2 4096 | stat 768
#define SMEM_RECUR (33280 * 4 + 33792 + 4096 + 768)

__global__ void __launch_bounds__(512, 1)
k_recur(const float* __restrict__ Whh, const float* __restrict__ bhh,
        const float* __restrict__ ghh, const float* __restrict__ behh) {
    extern __shared__ char smc[];
    __nv_bfloat16* Whi_s = (__nv_bfloat16*)smc;            // [32 r][520 k]
    __nv_bfloat16* Wlo_s = Whi_s + 32 * 520;
    __nv_bfloat16* Hhi_s = Wlo_s + 32 * 520;               // [32 b][520 k]
    __nv_bfloat16* Hlo_s = Hhi_s + 32 * 520;
    float* red  = (float*)(Hlo_s + 32 * 520);              // [8 ks][32 r][33]
    float* red2 = red + 8 * 32 * 33;                       // [16 w][2][32]
    float* stat = red2 + 1024;                             // 192 floats

    const int cta = blockIdx.x;          // 0..63
    const int l   = cta >> 4;
    const int cl  = cta & 15;
    const int r0  = cl * 32;
    const int tid = threadIdx.x;
    const int w   = tid >> 5;            // 16 warps
    const int lane = tid & 31;
    const int b   = lane;
    const int rb  = w & 1;               // row block (16 rows)
    const int ks  = w >> 1;              // k slice (16 k per quarter)

    // stationary W rows: fp32 -> split bf16 [r][k]
    const float* Wl = Whh + (size_t)l * HDIM * HDIM + (size_t)r0 * HDIM;
    for (int idx = tid; idx < 32 * 512; idx += 512) {
        int r = idx >> 9, k = idx & 511;
        float v = Wl[r * 512 + k];
        __nv_bfloat16 hi = __float2bfloat16(v);
        Whi_s[r * 520 + k] = hi;
        Wlo_s[r * 520 + k] = __float2bfloat16(v - __bfloat162float(hi));
    }

    // thread (w,b) owns rows r0+2w, r0+2w+1 for the epilogue
    const float bh0 = bhh[l * HDIM + r0 + 2 * w],  bh1 = bhh[l * HDIM + r0 + 2 * w + 1];
    const float gh0 = ghh[l * HDIM + r0 + 2 * w],  gh1 = ghh[l * HDIM + r0 + 2 * w + 1];
    const float be0 = behh[l * HDIM + r0 + 2 * w], be1 = behh[l * HDIM + r0 + 2 * w + 1];

    const unsigned* hline = g_hflag + l * 32;
    const unsigned* pline = g_pflag + l * 32;
    unsigned* my_hflag = g_hflag + l * 32 + cl;
    unsigned* my_pflag = g_pflag + l * 32 + cl;

    const unsigned Hhi_b = (unsigned)__cvta_generic_to_shared(Hhi_s);
    const unsigned Hlo_b = (unsigned)__cvta_generic_to_shared(Hlo_s);

    __syncthreads();

    for (int s = 0; s < TSTEPS; s++) {
        const __nv_bfloat16* hin_hi = g_hhi + (size_t)((s & 1) * LNUM + l) * (BSZ * HDIM);
        const __nv_bfloat16* hin_lo = g_hlo + (size_t)((s & 1) * LNUM + l) * (BSZ * HDIM);
        unsigned* hout_hi = (unsigned*)(g_hhi + (size_t)(((s + 1) & 1) * LNUM + l) * (BSZ * HDIM));
        unsigned* hout_lo = (unsigned*)(g_hlo + (size_t)(((s + 1) & 1) * LNUM + l) * (BSZ * HDIM));
        float* pb = g_part + (size_t)((s & 1) * LNUM + l) * (32 * 2 * BSZ);

        const float* aptr = g_A + ((size_t)l * TSTEPS + s) * HDIM * BSZ;
        float a0 = __ldcs(aptr + (size_t)(r0 + 2 * w) * BSZ + b);
        float a1 = __ldcs(aptr + (size_t)(r0 + 2 * w + 1) * BSZ + b);

        // issue one 128-k quarter of both split slabs (32 b x 256B each op)
        auto issue_q = [&](int Q) {
#pragma unroll
            for (int j = 0; j < 2; j++) {
                int t4 = j * 512 + tid;              // 0..1023
                int slab = t4 >> 9;                  // 0: hi, 1: lo
                int row = (t4 >> 4) & 31;
                int cch = t4 & 15;
                unsigned dst = (slab ? Hlo_b : Hhi_b)
                             + (unsigned)row * 1040u + (unsigned)Q * 256u + (unsigned)cch * 16u;
                const __nv_bfloat16* src = (slab ? hin_lo : hin_hi)
                                         + (size_t)row * 512 + Q * 128 + cch * 8;
                cpa16(dst, src);
            }
            CP_COMMIT();
        };

        float acc[4][4];
#pragma unroll
        for (int nf = 0; nf < 4; nf++)
#pragma unroll
            for (int r = 0; r < 4; r++) acc[nf][r] = 0.0f;

        // HMMA: warp (rb, ks) does rows [16rb,16rb+16) over 16-k slice of quarter Q
        auto mv = [&](int Q) {
            const int kc = Q * 128 + ks * 16 + (lane & 3) * 2;
            const int r_l = lane >> 2;
            int abase = (rb * 16 + r_l) * 520 + kc;
            uint32_t Ahi[4], Alo[4];
            Ahi[0] = *(const uint32_t*)(Whi_s + abase);
            Ahi[1] = *(const uint32_t*)(Whi_s + abase + 8 * 520);
            Ahi[2] = *(const uint32_t*)(Whi_s + abase + 8);
            Ahi[3] = *(const uint32_t*)(Whi_s + abase + 8 * 520 + 8);
            Alo[0] = *(const uint32_t*)(Wlo_s + abase);
            Alo[1] = *(const uint32_t*)(Wlo_s + abase + 8 * 520);
            Alo[2] = *(const uint32_t*)(Wlo_s + abase + 8);
            Alo[3] = *(const uint32_t*)(Wlo_s + abase + 8 * 520 + 8);
#pragma unroll
            for (int nf = 0; nf < 4; nf++) {
                int bbase = (nf * 8 + r_l) * 520 + kc;
                uint32_t Bhi[2], Blo[2];
                Bhi[0] = *(const uint32_t*)(Hhi_s + bbase);
                Bhi[1] = *(const uint32_t*)(Hhi_s + bbase + 8);
                Blo[0] = *(const uint32_t*)(Hlo_s + bbase);
                Blo[1] = *(const uint32_t*)(Hlo_s + bbase + 8);
                MMA16816(acc[nf], Ahi, Bhi);
                MMA16816(acc[nf], Ahi, Blo);
                MMA16816(acc[nf], Alo, Bhi);
            }
        };

        // quarter Q's k range [128Q,128Q+128) is produced by CTAs 4Q..4Q+3
        if (w == 0) poll4(hline, 0, (unsigned)s);
        __syncthreads();
        issue_q(0);
        if (w == 0) poll4(hline, 1, (unsigned)s);
        __syncthreads();
        issue_q(1);

        CP_WAIT(1); __syncthreads();
        mv(0);
        if (w == 0) poll4(hline, 2, (unsigned)s);
        __syncthreads();
        issue_q(2);

        CP_WAIT(1); __syncthreads();
        mv(1);
        if (w == 0) poll4(hline, 3, (unsigned)s);
        __syncthreads();
        issue_q(3);

        CP_WAIT(1); __syncthreads();
        mv(2);
        CP_WAIT(0); __syncthreads();
        mv(3);

        // ---- store warp partial accs to red[ks][rb*16+r][b] ----
        {
            const int rr = lane >> 2;
            const int bc = (lane & 3) * 2;
#pragma unroll
            for (int nf = 0; nf < 4; nf++) {
                int bb = nf * 8 + bc;
                red[(ks * 32 + rb * 16 + rr) * 33 + bb]         = acc[nf][0];
                red[(ks * 32 + rb * 16 + rr) * 33 + bb + 1]     = acc[nf][1];
                red[(ks * 32 + rb * 16 + rr + 8) * 33 + bb]     = acc[nf][2];
                red[(ks * 32 + rb * 16 + rr + 8) * 33 + bb + 1] = acc[nf][3];
            }
        }
        __syncthreads();

        // ---- z for own 2 rows (sum 8 k-slices) ----
        float z0 = bh0, z1 = bh1;
#pragma unroll
        for (int kk = 0; kk < 8; kk++) {
            z0 += red[(kk * 32 + 2 * w) * 33 + b];
            z1 += red[(kk * 32 + 2 * w + 1) * 33 + b];
        }
        red2[(w * 2 + 0) * 32 + b] = z0 + z1;
        red2[(w * 2 + 1) * 32 + b] = fmaf(z0, z0, z1 * z1);
        __syncthreads();

        // ---- warp 0 publishes CTA partials; warps 0-1 gather global stats ----
        if (w == 0) {
            float S = 0.f, Q = 0.f;
#pragma unroll
            for (int j = 0; j < 16; j++) { S += red2[(j * 2) * 32 + b]; Q += red2[(j * 2 + 1) * 32 + b]; }
            pb[cl * 64 + b]      = S;
            pb[cl * 64 + 32 + b] = Q;
            __syncwarp();
            if (b == 0) red_release_add1(my_pflag);
            poll16f(pline, (unsigned)(s + 1));
            float S2 = 0.f, Q2 = 0.f;
#pragma unroll 4
            for (int cc = 0; cc < 8; cc++) {
                S2 += __ldcg(pb + cc * 64 + b);
                Q2 += __ldcg(pb + cc * 64 + 32 + b);
            }
            stat[64 + b] = S2; stat[96 + b] = Q2;
        } else if (w == 1) {
            poll16f(pline, (unsigned)(s + 1));
            float S2 = 0.f, Q2 = 0.f;
#pragma unroll 4
            for (int cc = 8; cc < 16; cc++) {
                S2 += __ldcg(pb + cc * 64 + b);
                Q2 += __ldcg(pb + cc * 64 + 32 + b);
            }
            stat[128 + b] = S2; stat[160 + b] = Q2;
        }
        if (w < 2) {
            asm volatile("bar.sync 1, 64;" ::: "memory");
            if (w == 0) {
                float S = stat[64 + b] + stat[128 + b];
                float Q = stat[96 + b] + stat[160 + b];
                float mu = S * (1.0f / HDIM);
                float var = Q * (1.0f / HDIM) - mu * mu;
                stat[b] = mu;
                stat[32 + b] = rsqrtf(var + EPS);
            }
        }
        __syncthreads();

        // ---- h^{s+1} for own rows: tanh, split, packed u32 publish ----
        float mu = stat[b], rstd = stat[32 + b];
        float h0 = tanhf(a0 + (z0 - mu) * rstd * gh0 + be0);
        float h1 = tanhf(a1 + (z1 - mu) * rstd * gh1 + be1);
        __nv_bfloat16 h0hi = __float2bfloat16(h0);
        __nv_bfloat16 h1hi = __float2bfloat16(h1);
        __nv_bfloat16 h0lo = __float2bfloat16(h0 - __bfloat162float(h0hi));
        __nv_bfloat16 h1lo = __float2bfloat16(h1 - __bfloat162float(h1hi));
        unsigned hipack = (unsigned)bfbits(h0hi) | ((unsigned)bfbits(h1hi) << 16);
        unsigned lopack = (unsigned)bfbits(h0lo) | ((unsigned)bfbits(h1lo) << 16);
        int u32idx = b * 256 + cl * 16 + w;          // [b][k-pair]
        hout_hi[u32idx] = hipack;
        hout_lo[u32idx] = lopack;
        if (l == 3) {
            int h3idx = (s * 32 + b) * 256 + cl * 16 + w;
            ((unsigned*)g_H3hi)[h3idx] = hipack;
            ((unsigned*)g_H3lo)[h3idx] = lopack;
        }
        if (s == TSTEPS - 1) {
            g_h[(size_t)l * (HDIM * BSZ) + (size_t)(r0 + 2 * w) * BSZ + b]     = h0;
            g_h[(size_t)l * (HDIM * BSZ) + (size_t)(r0 + 2 * w + 1) * BSZ + b] = h1;
        }
        __syncthreads();
        if (tid == 0) red_release_add1(my_hflag);
    }
}

// ---------------- phase 3 (HMMA): out = h3 @ W_ho^T + b_ho + x --------------
__global__ __launch_bounds__(512) void k_gemm_out_mma(const float* __restrict__ bho,
                                                      const float* __restrict__ x,
                                                      float* __restrict__ out) {
    extern __shared__ char smem[];
    const unsigned sb = (unsigned)__cvta_generic_to_shared(smem);
    const int tid = threadIdx.x;
    const int lane = tid & 31;
    const int w = tid >> 5;
    const int wm = w >> 2, wn = w & 3;
    const int d0 = blockIdx.x * 128;
    const int n0 = blockIdx.y * 128;

    const __nv_bfloat16* gAhi = g_WOhi + (size_t)d0 * HDIM;
    const __nv_bfloat16* gAlo = g_WOlo + (size_t)d0 * HDIM;
    const __nv_bfloat16* gBhi = g_H3hi + (size_t)n0 * HDIM;
    const __nv_bfloat16* gBlo = g_H3lo + (size_t)n0 * HDIM;

    auto issue = [&](int c) {
        const unsigned stg = sb + (unsigned)(c & 1) * ZI_STAGE;
        const __nv_bfloat16* srcs[4] = {gAhi, gAlo, gBhi, gBlo};
#pragma unroll
        for (int op = 0; op < 4; op++) {
            const __nv_bfloat16* src = srcs[op] + c * 64;
            unsigned dst = stg + (unsigned)op * 18432u;
#pragma unroll
            for (int j = 0; j < 2; j++) {
                int idx = tid + j * 512;
                int r = idx >> 3, seg = idx & 7;
                cpa16(dst + (unsigned)r * 144u + (unsigned)seg * 16u,
                      src + (size_t)r * HDIM + seg * 8);
            }
        }
        CP_COMMIT();
    };

    float acc[2][4][4];
#pragma unroll
    for (int mt = 0; mt < 2; mt++)
#pragma unroll
        for (int nt = 0; nt < 4; nt++)
#pragma unroll
            for (int r = 0; r < 4; r++) acc[mt][nt][r] = 0.0f;

    issue(0); issue(1);

    for (int c = 0; c < 8; c++) {
        if (c == 7) { CP_WAIT(0); } else { CP_WAIT(1); }
        __syncthreads();

        const __nv_bfloat16* sAhi = (const __nv_bfloat16*)(smem + (c & 1) * ZI_STAGE);
        const __nv_bfloat16* sAlo = sAhi + 9216;
        const __nv_bfloat16* sBhi = sAhi + 18432;
        const __nv_bfloat16* sBlo = sAhi + 27648;

#pragma unroll
        for (int ks = 0; ks < 4; ks++) {
            const int kc = ks * 16 + (lane & 3) * 2;
            uint32_t ahi[2][4], alo[2][4];
#pragma unroll
            for (int mt = 0; mt < 2; mt++) {
                int base = (wm * 32 + mt * 16 + (lane >> 2)) * 72 + kc;
                ahi[mt][0] = *(const uint32_t*)(sAhi + base);
                ahi[mt][1] = *(const uint32_t*)(sAhi + base + 8 * 72);
                ahi[mt][2] = *(const uint32_t*)(sAhi + base + 8);
                ahi[mt][3] = *(const uint32_t*)(sAhi + base + 8 * 72 + 8);
                alo[mt][0] = *(const uint32_t*)(sAlo + base);
                alo[mt][1] = *(const uint32_t*)(sAlo + base + 8 * 72);
                alo[mt][2] = *(const uint32_t*)(sAlo + base + 8);
                alo[mt][3] = *(const uint32_t*)(sAlo + base + 8 * 72 + 8);
            }
            uint32_t bhi[4][2], blo[4][2];
#pragma unroll
            for (int nt = 0; nt < 4; nt++) {
                int base = (wn * 32 + nt * 8 + (lane >> 2)) * 72 + kc;
                bhi[nt][0] = *(const uint32_t*)(sBhi + base);
                bhi[nt][1] = *(const uint32_t*)(sBhi + base + 8);
                blo[nt][0] = *(const uint32_t*)(sBlo + base);
                blo[nt][1] = *(const uint32_t*)(sBlo + base + 8);
            }
#pragma unroll
            for (int mt = 0; mt < 2; mt++)
#pragma unroll
                for (int nt = 0; nt < 4; nt++) {
                    MMA16816(acc[mt][nt], ahi[mt], bhi[nt]);
                    MMA16816(acc[mt][nt], ahi[mt], blo[nt]);
                    MMA16816(acc[mt][nt], alo[mt], bhi[nt]);
                }
        }
        if (c < 6) { __syncthreads(); issue(c + 2); }
    }

    __syncthreads();
    float* s_out = (float*)smem;
#pragma unroll
    for (int mt = 0; mt < 2; mt++)
#pragma unroll
        for (int nt = 0; nt < 4; nt++) {
            int hr = wm * 32 + mt * 16 + (lane >> 2);
            int nc = wn * 32 + nt * 8 + (lane & 3) * 2;
            s_out[nc * 132 + hr]           = acc[mt][nt][0];
            s_out[(nc + 1) * 132 + hr]     = acc[mt][nt][1];
            s_out[nc * 132 + hr + 8]       = acc[mt][nt][2];
            s_out[(nc + 1) * 132 + hr + 8] = acc[mt][nt][3];
        }
    __syncthreads();

    for (int i = tid; i < 128 * 128; i += 512) {
        int n = i >> 7;
        int dd = i & 127;
        int tg = n >> 5, bb = n & 31;
        int t = (n0 >> 5) + tg;
        int d = d0 + dd;
        size_t oidx = ((size_t)bb * TSTEPS + t) * DDIM + d;
        out[oidx] = s_out[n * 132 + dd] + bho[d] + x[oidx];
    }
}

// ---------------- h_final: [L,B,H] from g_h ([l][h][b]) ---------------------
__global__ void k_hfinal(float* __restrict__ out2) {
    int idx = blockIdx.x * 256 + threadIdx.x;
    int l = idx >> 14;
    int rem = idx & 16383;
    int bb = rem >> 9;
    int hh = rem & 511;
    out2[idx] = g_h[(size_t)l * (HDIM * BSZ) + (size_t)hh * BSZ + bb];
}

// ---------------- launch -----------------------------------------------------
extern "C" void kernel_launch(void* const* d_in, const int* in_sizes, int n_in,
                              void* d_out, int out_size) {
    const float* x    = (const float*)d_in[0];
    const float* Wih  = (const float*)d_in[1];
    const float* bih  = (const float*)d_in[2];
    const float* gih  = (const float*)d_in[3];
    const float* beih = (const float*)d_in[4];
    const float* Whh  = (const float*)d_in[5];
    const float* bhh  = (const float*)d_in[6];
    const float* ghh  = (const float*)d_in[7];
    const float* behh = (const float*)d_in[8];
    const float* Who  = (const float*)d_in[9];
    const float* bho  = (const float*)d_in[10];
    float* out = (float*)d_out;

    cudaFuncSetAttribute(k_recur, cudaFuncAttributeMaxDynamicSharedMemorySize, SMEM_RECUR);
    cudaFuncSetAttribute(k_gemm_zi_mma, cudaFuncAttributeMaxDynamicSharedMemorySize, ZI_SMEM);
    cudaFuncSetAttribute(k_gemm_out_mma, cudaFuncAttributeMaxDynamicSharedMemorySize, ZI_SMEM);

    k_init<<<64, 256>>>();
    {   // W_ih split
        __nv_bfloat16 *dhi, *dlo;
        cudaGetSymbolAddress((void**)&dhi, g_Whi);
        cudaGetSymbolAddress((void**)&dlo, g_Wlo);
        int n4 = LNUM * HDIM * DDIM / 4;
        k_cvt_split<<<(n4 + 255) / 256, 256>>>(Wih, dhi, dlo, n4);
    }
    {   // W_ho split
        __nv_bfloat16 *dhi, *dlo;
        cudaGetSymbolAddress((void**)&dhi, g_WOhi);
        cudaGetSymbolAddress((void**)&dlo, g_WOlo);
        int n4 = DDIM * HDIM / 4;
        k_cvt_split<<<(n4 + 255) / 256, 256>>>(Who, dhi, dlo, n4);
    }
    k_cvt_x<<<(TSTEPS * BSZ * DDIM / 4 + 255) / 256, 256>>>(x);
    k_gemm_zi_mma<<<dim3(16, 512), 512, ZI_SMEM>>>(bih);
    k_ln<<<LNUM * TSTEPS, 256>>>(gih, beih);
    k_recur<<<64, 512, SMEM_RECUR>>>(Whh, bhh, ghh, behh);
    k_gemm_out_mma<<<dim3(4, 512), 512, ZI_SMEM>>>(bho, x, out);
    k_hfinal<<<256, 256>>>(out + (size_t)BSZ * TSTEPS * DDIM);
}

// round 16
// speedup vs baseline: 1.7507x; 1.1284x over previous
#include <cuda_runtime.h>
#include <cuda_bf16.h>
#include <math.h>
#include <cstdint>

#define LNUM 4
#define DDIM 512
#define HDIM 512
#define BSZ  32
#define TSTEPS 2048
#define EPS 1e-5f
#define NCTA 128   // 4 layers x 32 CTAs, 16 rows each

// ---------------- device scratch -------------------------------------------
__device__ float g_A[(size_t)LNUM * TSTEPS * HDIM * BSZ];   // LN(zi): [l][t][h][b]
__device__ float g_h[LNUM * HDIM * BSZ];                    // final h (fp32, [l][h][b])
__device__ float g_part[2 * LNUM * 32 * 2 * BSZ];           // [p][l][cta][S/Q][b]
__device__ __align__(128) unsigned g_hflag[LNUM * 32];
__device__ __align__(128) unsigned g_pflag[LNUM * 32];
// split-bf16 operands
__device__ __nv_bfloat16 g_Xhi[(size_t)TSTEPS * BSZ * DDIM]; // [n=t*32+b][d]
__device__ __nv_bfloat16 g_Xlo[(size_t)TSTEPS * BSZ * DDIM];
__device__ __nv_bfloat16 g_Whi[(size_t)LNUM * HDIM * DDIM];
__device__ __nv_bfloat16 g_Wlo[(size_t)LNUM * HDIM * DDIM];
__device__ __nv_bfloat16 g_WOhi[(size_t)DDIM * HDIM];
__device__ __nv_bfloat16 g_WOlo[(size_t)DDIM * HDIM];
// split h state, double-buffered by parity: [p][l][b][k]
__device__ __nv_bfloat16 g_hhi[2 * LNUM * BSZ * HDIM];
__device__ __nv_bfloat16 g_hlo[2 * LNUM * BSZ * HDIM];
// split layer-3 h: [n=t*32+b][k=h]
__device__ __nv_bfloat16 g_H3hi[(size_t)TSTEPS * BSZ * HDIM];
__device__ __nv_bfloat16 g_H3lo[(size_t)TSTEPS * BSZ * HDIM];

// ---------------- primitives ------------------------------------------------
__device__ __forceinline__ unsigned ld_acq(const unsigned* p) {
    unsigned v;
    asm volatile("ld.acquire.gpu.global.u32 %0, [%1];" : "=r"(v) : "l"(p) : "memory");
    return v;
}
__device__ __forceinline__ void red_release_add1(unsigned* p) {
    asm volatile("red.release.gpu.global.add.u32 [%0], 1;" :: "l"(p) : "memory");
}
__device__ __forceinline__ void cpa16(unsigned dst, const void* src) {
    asm volatile("cp.async.cg.shared.global [%0], [%1], 16;" :: "r"(dst), "l"(src) : "memory");
}
#define CP_COMMIT() asm volatile("cp.async.commit_group;" ::: "memory")
#define CP_WAIT(N)  asm volatile("cp.async.wait_group %0;" :: "n"(N) : "memory")

__device__ __forceinline__ void poll8(const unsigned* line, int grp, unsigned tgt) {
    const unsigned* f = line + grp * 8 + (threadIdx.x & 7);
    while (!__all_sync(0xffffffffu, ld_acq(f) >= tgt)) {}
}
__device__ __forceinline__ void poll32(const unsigned* line, unsigned tgt) {
    const unsigned* f = line + (threadIdx.x & 31);
    while (!__all_sync(0xffffffffu, ld_acq(f) >= tgt)) {}
}

// warp-level bf16 MMA (sm_80+, arch-unconditional PTX)
#define MMA16816(d, a, b) \
    asm volatile("mma.sync.aligned.m16n8k16.row.col.f32.bf16.bf16.f32 " \
        "{%0,%1,%2,%3}, {%4,%5,%6,%7}, {%8,%9}, {%0,%1,%2,%3};" \
        : "+f"((d)[0]), "+f"((d)[1]), "+f"((d)[2]), "+f"((d)[3]) \
        : "r"((a)[0]), "r"((a)[1]), "r"((a)[2]), "r"((a)[3]), \
          "r"((b)[0]), "r"((b)[1]))

__device__ __forceinline__ unsigned short bfbits(__nv_bfloat16 h) {
    return __bfloat16_as_ushort(h);
}

// ---------------- init: reset per launch (graph replays!) -------------------
__global__ void k_init() {
    int idx = blockIdx.x * blockDim.x + threadIdx.x;
    if (idx < LNUM * 32) { g_hflag[idx] = 0u; g_pflag[idx] = 0u; }
    unsigned* hh = (unsigned*)g_hhi;
    unsigned* hl = (unsigned*)g_hlo;
    for (int i = idx; i < 2 * LNUM * BSZ * HDIM / 2; i += gridDim.x * blockDim.x) {
        hh[i] = 0u; hl[i] = 0u;
    }
}

// ---------------- split conversions -----------------------------------------
__global__ void k_cvt_split(const float* __restrict__ W, __nv_bfloat16* dhi,
                            __nv_bfloat16* dlo, int n4) {
    int i4 = blockIdx.x * 256 + threadIdx.x;
    if (i4 >= n4) return;
    size_t e = (size_t)i4 * 4;
    float4 v = *(const float4*)(W + e);
    float vv[4] = {v.x, v.y, v.z, v.w};
    __nv_bfloat16 h[4], lo[4];
#pragma unroll
    for (int j = 0; j < 4; j++) {
        h[j]  = __float2bfloat16(vv[j]);
        lo[j] = __float2bfloat16(vv[j] - __bfloat162float(h[j]));
    }
    __nv_bfloat162* dh = (__nv_bfloat162*)(dhi + e);
    __nv_bfloat162* dl = (__nv_bfloat162*)(dlo + e);
    __nv_bfloat162 p;
    p.x = h[0];  p.y = h[1];  dh[0] = p;
    p.x = h[2];  p.y = h[3];  dh[1] = p;
    p.x = lo[0]; p.y = lo[1]; dl[0] = p;
    p.x = lo[2]; p.y = lo[3]; dl[1] = p;
}

__global__ void k_cvt_x(const float* __restrict__ x) {
    size_t e = ((size_t)blockIdx.x * 256 + threadIdx.x) * 4;
    if (e >= (size_t)TSTEPS * BSZ * DDIM) return;
    int n = (int)(e >> 9), d = (int)(e & 511);
    int t = n >> 5, b = n & 31;
    float4 v = *(const float4*)(x + ((size_t)b * TSTEPS + t) * DDIM + d);
    float vv[4] = {v.x, v.y, v.z, v.w};
    __nv_bfloat16 h[4], lo[4];
#pragma unroll
    for (int j = 0; j < 4; j++) {
        h[j]  = __float2bfloat16(vv[j]);
        lo[j] = __float2bfloat16(vv[j] - __bfloat162float(h[j]));
    }
    __nv_bfloat162* dh = (__nv_bfloat162*)(g_Xhi + e);
    __nv_bfloat162* dl = (__nv_bfloat162*)(g_Xlo + e);
    __nv_bfloat162 p;
    p.x = h[0];  p.y = h[1];  dh[0] = p;
    p.x = h[2];  p.y = h[3];  dh[1] = p;
    p.x = lo[0]; p.y = lo[1]; dl[0] = p;
    p.x = lo[2]; p.y = lo[3]; dl[1] = p;
}

// ---------------- phase 1 (HMMA): Zi = W_ih @ X^T + b_ih --------------------
#define ZI_STAGE  73728                 // 4 * 128*72*2 bytes
#define ZI_SMEM   (2 * ZI_STAGE)

__global__ __launch_bounds__(512) void k_gemm_zi_mma(const float* __restrict__ bih) {
    extern __shared__ char smem[];
    const unsigned sb = (unsigned)__cvta_generic_to_shared(smem);
    const int tid = threadIdx.x;
    const int lane = tid & 31;
    const int w = tid >> 5;
    const int wm = w >> 2, wn = w & 3;
    const int l  = blockIdx.x >> 2;
    const int h0 = (blockIdx.x & 3) * 128;
    const int n0 = blockIdx.y * 128;

    const __nv_bfloat16* gAhi = g_Whi + ((size_t)l * HDIM + h0) * DDIM;
    const __nv_bfloat16* gAlo = g_Wlo + ((size_t)l * HDIM + h0) * DDIM;
    const __nv_bfloat16* gBhi = g_Xhi + (size_t)n0 * DDIM;
    const __nv_bfloat16* gBlo = g_Xlo + (size_t)n0 * DDIM;

    auto issue = [&](int c) {
        const unsigned stg = sb + (unsigned)(c & 1) * ZI_STAGE;
        const __nv_bfloat16* srcs[4] = {gAhi, gAlo, gBhi, gBlo};
#pragma unroll
        for (int op = 0; op < 4; op++) {
            const __nv_bfloat16* src = srcs[op] + c * 64;
            unsigned dst = stg + (unsigned)op * 18432u;
#pragma unroll
            for (int j = 0; j < 2; j++) {
                int idx = tid + j * 512;
                int r = idx >> 3, seg = idx & 7;
                cpa16(dst + (unsigned)r * 144u + (unsigned)seg * 16u,
                      src + (size_t)r * DDIM + seg * 8);
            }
        }
        CP_COMMIT();
    };

    float acc[2][4][4];
#pragma unroll
    for (int mt = 0; mt < 2; mt++)
#pragma unroll
        for (int nt = 0; nt < 4; nt++)
#pragma unroll
            for (int r = 0; r < 4; r++) acc[mt][nt][r] = 0.0f;

    issue(0); issue(1);

    for (int c = 0; c < 8; c++) {
        if (c == 7) { CP_WAIT(0); } else { CP_WAIT(1); }
        __syncthreads();

        const __nv_bfloat16* sAhi = (const __nv_bfloat16*)(smem + (c & 1) * ZI_STAGE);
        const __nv_bfloat16* sAlo = sAhi + 9216;
        const __nv_bfloat16* sBhi = sAhi + 18432;
        const __nv_bfloat16* sBlo = sAhi + 27648;

#pragma unroll
        for (int ks = 0; ks < 4; ks++) {
            const int kc = ks * 16 + (lane & 3) * 2;
            uint32_t ahi[2][4], alo[2][4];
#pragma unroll
            for (int mt = 0; mt < 2; mt++) {
                int base = (wm * 32 + mt * 16 + (lane >> 2)) * 72 + kc;
                ahi[mt][0] = *(const uint32_t*)(sAhi + base);
                ahi[mt][1] = *(const uint32_t*)(sAhi + base + 8 * 72);
                ahi[mt][2] = *(const uint32_t*)(sAhi + base + 8);
                ahi[mt][3] = *(const uint32_t*)(sAhi + base + 8 * 72 + 8);
                alo[mt][0] = *(const uint32_t*)(sAlo + base);
                alo[mt][1] = *(const uint32_t*)(sAlo + base + 8 * 72);
                alo[mt][2] = *(const uint32_t*)(sAlo + base + 8);
                alo[mt][3] = *(const uint32_t*)(sAlo + base + 8 * 72 + 8);
            }
            uint32_t bhi[4][2], blo[4][2];
#pragma unroll
            for (int nt = 0; nt < 4; nt++) {
                int base = (wn * 32 + nt * 8 + (lane >> 2)) * 72 + kc;
                bhi[nt][0] = *(const uint32_t*)(sBhi + base);
                bhi[nt][1] = *(const uint32_t*)(sBhi + base + 8);
                blo[nt][0] = *(const uint32_t*)(sBlo + base);
                blo[nt][1] = *(const uint32_t*)(sBlo + base + 8);
            }
#pragma unroll
            for (int mt = 0; mt < 2; mt++)
#pragma unroll
                for (int nt = 0; nt < 4; nt++) {
                    MMA16816(acc[mt][nt], ahi[mt], bhi[nt]);
                    MMA16816(acc[mt][nt], ahi[mt], blo[nt]);
                    MMA16816(acc[mt][nt], alo[mt], bhi[nt]);
                }
        }
        if (c < 6) { __syncthreads(); issue(c + 2); }
    }

    __syncthreads();
    float* s_out = (float*)smem;
#pragma unroll
    for (int mt = 0; mt < 2; mt++)
#pragma unroll
        for (int nt = 0; nt < 4; nt++) {
            int hr = wm * 32 + mt * 16 + (lane >> 2);
            int nc = wn * 32 + nt * 8 + (lane & 3) * 2;
            s_out[hr * 132 + nc]           = acc[mt][nt][0];
            s_out[hr * 132 + nc + 1]       = acc[mt][nt][1];
            s_out[(hr + 8) * 132 + nc]     = acc[mt][nt][2];
            s_out[(hr + 8) * 132 + nc + 1] = acc[mt][nt][3];
        }
    __syncthreads();

    for (int i = tid; i < 4 * 128 * 32; i += 512) {
        int tg = i >> 12;
        int h  = (i >> 5) & 127;
        int b  = i & 31;
        float bi = bih[l * HDIM + h0 + h];
        int t = (n0 >> 5) + tg;
        g_A[((size_t)(l * TSTEPS + t) * HDIM + h0 + h) * BSZ + b] =
            s_out[h * 132 + tg * 32 + b] + bi;
    }
}

// ---------------- LN over h for each (l,t,b), in place on g_A ---------------
__global__ __launch_bounds__(256) void k_ln(const float* __restrict__ gih,
                                            const float* __restrict__ beih) {
    const int lt = blockIdx.x;
    const int l  = lt >> 11;
    const size_t base = (size_t)lt * HDIM * BSZ;
    const int tid = threadIdx.x;
    const int b = tid & 31, w = tid >> 5;

    float v[64];
    float s = 0.0f, q = 0.0f;
#pragma unroll
    for (int i = 0; i < 64; i++) {
        float xv = g_A[base + (size_t)(w * 64 + i) * BSZ + b];
        v[i] = xv;
        s += xv;
        q = fmaf(xv, xv, q);
    }
    __shared__ float rs[8][32], rq[8][32], mu_s[32], rstd_s[32];
    rs[w][b] = s; rq[w][b] = q;
    __syncthreads();
    if (w == 0) {
        float ss = 0.0f, qq = 0.0f;
#pragma unroll
        for (int j = 0; j < 8; j++) { ss += rs[j][b]; qq += rq[j][b]; }
        float mu = ss * (1.0f / HDIM);
        float var = qq * (1.0f / HDIM) - mu * mu;
        mu_s[b] = mu;
        rstd_s[b] = rsqrtf(var + EPS);
    }
    __syncthreads();
    float mu = mu_s[b], rstd = rstd_s[b];
#pragma unroll
    for (int i = 0; i < 64; i++) {
        int h = w * 64 + i;
        g_A[base + (size_t)h * BSZ + b] =
            (v[i] - mu) * rstd * gih[l * HDIM + h] + beih[l * HDIM + h];
    }
}

// ---------------- phase 2: HMMA dataflow recurrence (r13 base, leaner sync) --
// SMEM bytes: Whi 16640 | Wlo 16640 | Hhi 33280 | Hlo 33280 | red 16896 | red2 2048 | stat 768
#define SMEM_RECUR (16640 * 2 + 33280 * 2 + 16896 + 2048 + 768)

__global__ void __launch_bounds__(256, 1)
k_recur(const float* __restrict__ Whh, const float* __restrict__ bhh,
        const float* __restrict__ ghh, const float* __restrict__ behh) {
    extern __shared__ char smc[];
    __nv_bfloat16* Whi_s = (__nv_bfloat16*)smc;            // [16][520]
    __nv_bfloat16* Wlo_s = Whi_s + 16 * 520;
    __nv_bfloat16* Hhi_s = Wlo_s + 16 * 520;               // [32 b][520 k]
    __nv_bfloat16* Hlo_s = Hhi_s + 32 * 520;
    float* red  = (float*)(Hlo_s + 32 * 520);              // [8 w][16 r][33]
    float* red2 = red + 8 * 16 * 33;                       // [8 w][2][32]
    float* stat = red2 + 512;

    const int cta = blockIdx.x;
    const int l   = cta >> 5;
    const int cl  = cta & 31;
    const int r0  = cl * 16;
    const int tid = threadIdx.x;
    const int w   = tid >> 5;
    const int lane = tid & 31;
    const int b   = lane;

    // ---- stationary W rows: fp32 -> split bf16 in smem [r][k] ----
    const float* Wl = Whh + (size_t)l * HDIM * HDIM + (size_t)r0 * HDIM;
    for (int idx = tid; idx < 16 * 512; idx += 256) {
        int r = idx >> 9, k = idx & 511;
        float v = Wl[r * 512 + k];
        __nv_bfloat16 hi = __float2bfloat16(v);
        Whi_s[r * 520 + k] = hi;
        Wlo_s[r * 520 + k] = __float2bfloat16(v - __bfloat162float(hi));
    }

    // thread (w,b) owns rows r0+2w, r0+2w+1
    const float bh0 = bhh[l * HDIM + r0 + 2 * w],  bh1 = bhh[l * HDIM + r0 + 2 * w + 1];
    const float gh0 = ghh[l * HDIM + r0 + 2 * w],  gh1 = ghh[l * HDIM + r0 + 2 * w + 1];
    const float be0 = behh[l * HDIM + r0 + 2 * w], be1 = behh[l * HDIM + r0 + 2 * w + 1];

    const unsigned* hline = g_hflag + l * 32;
    const unsigned* pline = g_pflag + l * 32;
    unsigned* my_hflag = g_hflag + l * 32 + cl;
    unsigned* my_pflag = g_pflag + l * 32 + cl;

    const unsigned Hhi_base = (unsigned)__cvta_generic_to_shared(Hhi_s);
    const unsigned Hlo_base = (unsigned)__cvta_generic_to_shared(Hlo_s);

    __syncthreads();

    for (int s = 0; s < TSTEPS; s++) {
        const __nv_bfloat16* hin_hi = g_hhi + (size_t)((s & 1) * LNUM + l) * (BSZ * HDIM);
        const __nv_bfloat16* hin_lo = g_hlo + (size_t)((s & 1) * LNUM + l) * (BSZ * HDIM);
        unsigned* hout_hi = (unsigned*)(g_hhi + (size_t)(((s + 1) & 1) * LNUM + l) * (BSZ * HDIM));
        unsigned* hout_lo = (unsigned*)(g_hlo + (size_t)(((s + 1) & 1) * LNUM + l) * (BSZ * HDIM));
        float* pb = g_part + (size_t)((s & 1) * LNUM + l) * (32 * 2 * BSZ);

        const float* aptr = g_A + ((size_t)l * TSTEPS + s) * HDIM * BSZ;
        float a0 = __ldcs(aptr + (size_t)(r0 + 2 * w) * BSZ + b);
        float a1 = __ldcs(aptr + (size_t)(r0 + 2 * w + 1) * BSZ + b);

        // issue one 128-k quarter of both split slabs (32 rows x 256B each)
        auto issue_q = [&](int Q) {
#pragma unroll
            for (int j = 0; j < 4; j++) {
                int t4 = j * 256 + tid;              // 0..1023
                int slab = t4 >> 9;                  // 0: hi, 1: lo
                int row = (t4 >> 4) & 31;
                int cch = t4 & 15;
                unsigned dst = (slab ? Hlo_base : Hhi_base)
                             + (unsigned)row * 1040u + (unsigned)Q * 256u + (unsigned)cch * 16u;
                const __nv_bfloat16* src = (slab ? hin_lo : hin_hi)
                                         + (size_t)row * 512 + Q * 128 + cch * 8;
                cpa16(dst, src);
            }
            CP_COMMIT();
        };

        float acc[4][4];
#pragma unroll
        for (int nf = 0; nf < 4; nf++)
#pragma unroll
            for (int r = 0; r < 4; r++) acc[nf][r] = 0.0f;

        // HMMA over this warp's 16-k slice of quarter Q
        auto mv = [&](int Q) {
            const int kc = Q * 128 + w * 16 + (lane & 3) * 2;
            const int r_l = lane >> 2;
            int abase = r_l * 520 + kc;
            uint32_t Ahi[4], Alo[4];
            Ahi[0] = *(const uint32_t*)(Whi_s + abase);
            Ahi[1] = *(const uint32_t*)(Whi_s + abase + 8 * 520);
            Ahi[2] = *(const uint32_t*)(Whi_s + abase + 8);
            Ahi[3] = *(const uint32_t*)(Whi_s + abase + 8 * 520 + 8);
            Alo[0] = *(const uint32_t*)(Wlo_s + abase);
            Alo[1] = *(const uint32_t*)(Wlo_s + abase + 8 * 520);
            Alo[2] = *(const uint32_t*)(Wlo_s + abase + 8);
            Alo[3] = *(const uint32_t*)(Wlo_s + abase + 8 * 520 + 8);
#pragma unroll
            for (int nf = 0; nf < 4; nf++) {
                int bbase = (nf * 8 + r_l) * 520 + kc;
                uint32_t Bhi[2], Blo[2];
                Bhi[0] = *(const uint32_t*)(Hhi_s + bbase);
                Bhi[1] = *(const uint32_t*)(Hhi_s + bbase + 8);
                Blo[0] = *(const uint32_t*)(Hlo_s + bbase);
                Blo[1] = *(const uint32_t*)(Hlo_s + bbase + 8);
                MMA16816(acc[nf], Ahi, Bhi);
                MMA16816(acc[nf], Ahi, Blo);
                MMA16816(acc[nf], Alo, Bhi);
            }
        };

        // ---- leaner ladder: paired polls/issues, 6 syncs instead of 12 ----
        if (w == 0) { poll8(hline, 0, (unsigned)s); poll8(hline, 1, (unsigned)s); }
        __syncthreads();
        issue_q(0); issue_q(1);

        CP_WAIT(1); __syncthreads();         // q0 ready
        mv(0);
        if (w == 0) { poll8(hline, 2, (unsigned)s); poll8(hline, 3, (unsigned)s); }
        __syncthreads();
        issue_q(2); issue_q(3);

        CP_WAIT(2); __syncthreads();         // q1 ready
        mv(1);
        CP_WAIT(1); __syncthreads();         // q2 ready
        mv(2);
        CP_WAIT(0); __syncthreads();         // q3 ready
        mv(3);

        // ---- store warp partial accs to red[w][r][b] ----
        {
            const int rr = lane >> 2;
            const int bc = (lane & 3) * 2;
#pragma unroll
            for (int nf = 0; nf < 4; nf++) {
                int bb = nf * 8 + bc;
                red[(w * 16 + rr) * 33 + bb]         = acc[nf][0];
                red[(w * 16 + rr) * 33 + bb + 1]     = acc[nf][1];
                red[(w * 16 + rr + 8) * 33 + bb]     = acc[nf][2];
                red[(w * 16 + rr + 8) * 33 + bb + 1] = acc[nf][3];
            }
        }
        __syncthreads();

        // ---- z for own 2 rows (sum 8 warp k-slices) ----
        float z0 = bh0, z1 = bh1;
#pragma unroll
        for (int wp = 0; wp < 8; wp++) {
            z0 += red[(wp * 16 + 2 * w) * 33 + b];
            z1 += red[(wp * 16 + 2 * w + 1) * 33 + b];
        }
        red2[(w * 2 + 0) * 32 + b] = z0 + z1;
        red2[(w * 2 + 1) * 32 + b] = fmaf(z0, z0, z1 * z1);
        __syncthreads();

        // ---- warp 0 publishes CTA partials; warps 0-1 gather global stats ----
        if (w == 0) {
            float S = 0.f, Q = 0.f;
#pragma unroll
            for (int j = 0; j < 8; j++) { S += red2[(j * 2) * 32 + b]; Q += red2[(j * 2 + 1) * 32 + b]; }
            pb[cl * 64 + b]      = S;
            pb[cl * 64 + 32 + b] = Q;
            __syncwarp();
            if (b == 0) red_release_add1(my_pflag);
            poll32(pline, (unsigned)(s + 1));
            float S2 = 0.f, Q2 = 0.f;
#pragma unroll 4
            for (int cc = 0; cc < 16; cc++) {
                S2 += __ldcg(pb + cc * 64 + b);
                Q2 += __ldcg(pb + cc * 64 + 32 + b);
            }
            stat[64 + b] = S2; stat[96 + b] = Q2;
        } else if (w == 1) {
            poll32(pline, (unsigned)(s + 1));
            float S2 = 0.f, Q2 = 0.f;
#pragma unroll 4
            for (int cc = 16; cc < 32; cc++) {
                S2 += __ldcg(pb + cc * 64 + b);
                Q2 += __ldcg(pb + cc * 64 + 32 + b);
            }
            stat[128 + b] = S2; stat[160 + b] = Q2;
        }
        if (w < 2) {
            asm volatile("bar.sync 1, 64;" ::: "memory");
            if (w == 0) {
                float S = stat[64 + b] + stat[128 + b];
                float Q = stat[96 + b] + stat[160 + b];
                float mu = S * (1.0f / HDIM);
                float var = Q * (1.0f / HDIM) - mu * mu;
                stat[b] = mu;
                stat[32 + b] = rsqrtf(var + EPS);
            }
        }
        __syncthreads();

        // ---- h^{s+1} for own rows: tanh, split, packed u32 publish ----
        float mu = stat[b], rstd = stat[32 + b];
        float h0 = tanhf(a0 + (z0 - mu) * rstd * gh0 + be0);
        float h1 = tanhf(a1 + (z1 - mu) * rstd * gh1 + be1);
        __nv_bfloat16 h0hi = __float2bfloat16(h0);
        __nv_bfloat16 h1hi = __float2bfloat16(h1);
        __nv_bfloat16 h0lo = __float2bfloat16(h0 - __bfloat162float(h0hi));
        __nv_bfloat16 h1lo = __float2bfloat16(h1 - __bfloat162float(h1hi));
        unsigned hipack = (unsigned)bfbits(h0hi) | ((unsigned)bfbits(h1hi) << 16);
        unsigned lopack = (unsigned)bfbits(h0lo) | ((unsigned)bfbits(h1lo) << 16);
        int u32idx = b * 256 + cl * 8 + w;          // [b][k-pair]
        hout_hi[u32idx] = hipack;
        hout_lo[u32idx] = lopack;
        __syncthreads();
        if (tid == 0) red_release_add1(my_hflag);

        // ---- off-critical-path stores (not protocol-visible) ----
        if (l == 3) {
            int h3idx = (s * 32 + b) * 256 + cl * 8 + w;
            ((unsigned*)g_H3hi)[h3idx] = hipack;
            ((unsigned*)g_H3lo)[h3idx] = lopack;
        }
        if (s == TSTEPS - 1) {
            g_h[(size_t)l * (HDIM * BSZ) + (size_t)(r0 + 2 * w) * BSZ + b]     = h0;
            g_h[(size_t)l * (HDIM * BSZ) + (size_t)(r0 + 2 * w + 1) * BSZ + b] = h1;
        }
    }
}

// ---------------- phase 3 (HMMA): out = h3 @ W_ho^T + b_ho + x --------------
__global__ __launch_bounds__(512) void k_gemm_out_mma(const float* __restrict__ bho,
                                                      const float* __restrict__ x,
                                                      float* __restrict__ out) {
    extern __shared__ char smem[];
    const unsigned sb = (unsigned)__cvta_generic_to_shared(smem);
    const int tid = threadIdx.x;
    const int lane = tid & 31;
    const int w = tid >> 5;
    const int wm = w >> 2, wn = w & 3;
    const int d0 = blockIdx.x * 128;
    const int n0 = blockIdx.y * 128;

    const __nv_bfloat16* gAhi = g_WOhi + (size_t)d0 * HDIM;
    const __nv_bfloat16* gAlo = g_WOlo + (size_t)d0 * HDIM;
    const __nv_bfloat16* gBhi = g_H3hi + (size_t)n0 * HDIM;
    const __nv_bfloat16* gBlo = g_H3lo + (size_t)n0 * HDIM;

    auto issue = [&](int c) {
        const unsigned stg = sb + (unsigned)(c & 1) * ZI_STAGE;
        const __nv_bfloat16* srcs[4] = {gAhi, gAlo, gBhi, gBlo};
#pragma unroll
        for (int op = 0; op < 4; op++) {
            const __nv_bfloat16* src = srcs[op] + c * 64;
            unsigned dst = stg + (unsigned)op * 18432u;
#pragma unroll
            for (int j = 0; j < 2; j++) {
                int idx = tid + j * 512;
                int r = idx >> 3, seg = idx & 7;
                cpa16(dst + (unsigned)r * 144u + (unsigned)seg * 16u,
                      src + (size_t)r * HDIM + seg * 8);
            }
        }
        CP_COMMIT();
    };

    float acc[2][4][4];
#pragma unroll
    for (int mt = 0; mt < 2; mt++)
#pragma unroll
        for (int nt = 0; nt < 4; nt++)
#pragma unroll
            for (int r = 0; r < 4; r++) acc[mt][nt][r] = 0.0f;

    issue(0); issue(1);

    for (int c = 0; c < 8; c++) {
        if (c == 7) { CP_WAIT(0); } else { CP_WAIT(1); }
        __syncthreads();

        const __nv_bfloat16* sAhi = (const __nv_bfloat16*)(smem + (c & 1) * ZI_STAGE);
        const __nv_bfloat16* sAlo = sAhi + 9216;
        const __nv_bfloat16* sBhi = sAhi + 18432;
        const __nv_bfloat16* sBlo = sAhi + 27648;

#pragma unroll
        for (int ks = 0; ks < 4; ks++) {
            const int kc = ks * 16 + (lane & 3) * 2;
            uint32_t ahi[2][4], alo[2][4];
#pragma unroll
            for (int mt = 0; mt < 2; mt++) {
                int base = (wm * 32 + mt * 16 + (lane >> 2)) * 72 + kc;
                ahi[mt][0] = *(const uint32_t*)(sAhi + base);
                ahi[mt][1] = *(const uint32_t*)(sAhi + base + 8 * 72);
                ahi[mt][2] = *(const uint32_t*)(sAhi + base + 8);
                ahi[mt][3] = *(const uint32_t*)(sAhi + base + 8 * 72 + 8);
                alo[mt][0] = *(const uint32_t*)(sAlo + base);
                alo[mt][1] = *(const uint32_t*)(sAlo + base + 8 * 72);
                alo[mt][2] = *(const uint32_t*)(sAlo + base + 8);
                alo[mt][3] = *(const uint32_t*)(sAlo + base + 8 * 72 + 8);
            }
            uint32_t bhi[4][2], blo[4][2];
#pragma unroll
            for (int nt = 0; nt < 4; nt++) {
                int base = (wn * 32 + nt * 8 + (lane >> 2)) * 72 + kc;
                bhi[nt][0] = *(const uint32_t*)(sBhi + base);
                bhi[nt][1] = *(const uint32_t*)(sBhi + base + 8);
                blo[nt][0] = *(const uint32_t*)(sBlo + base);
                blo[nt][1] = *(const uint32_t*)(sBlo + base + 8);
            }
#pragma unroll
            for (int mt = 0; mt < 2; mt++)
#pragma unroll
                for (int nt = 0; nt < 4; nt++) {
                    MMA16816(acc[mt][nt], ahi[mt], bhi[nt]);
                    MMA16816(acc[mt][nt], ahi[mt], blo[nt]);
                    MMA16816(acc[mt][nt], alo[mt], bhi[nt]);
                }
        }
        if (c < 6) { __syncthreads(); issue(c + 2); }
    }

    // epilogue: stage as s_out[n][132] so global stores are d-contiguous
    __syncthreads();
    float* s_out = (float*)smem;
#pragma unroll
    for (int mt = 0; mt < 2; mt++)
#pragma unroll
        for (int nt = 0; nt < 4; nt++) {
            int hr = wm * 32 + mt * 16 + (lane >> 2);
            int nc = wn * 32 + nt * 8 + (lane & 3) * 2;
            s_out[nc * 132 + hr]           = acc[mt][nt][0];
            s_out[(nc + 1) * 132 + hr]     = acc[mt][nt][1];
            s_out[nc * 132 + hr + 8]       = acc[mt][nt][2];
            s_out[(nc + 1) * 132 + hr + 8] = acc[mt][nt][3];
        }
    __syncthreads();

    for (int i = tid; i < 128 * 128; i += 512) {
        int n = i >> 7;
        int dd = i & 127;
        int tg = n >> 5, bb = n & 31;
        int t = (n0 >> 5) + tg;
        int d = d0 + dd;
        size_t oidx = ((size_t)bb * TSTEPS + t) * DDIM + d;
        out[oidx] = s_out[n * 132 + dd] + bho[d] + x[oidx];
    }
}

// ---------------- h_final: [L,B,H] from g_h ([l][h][b]) ---------------------
__global__ void k_hfinal(float* __restrict__ out2) {
    int idx = blockIdx.x * 256 + threadIdx.x;
    int l = idx >> 14;
    int rem = idx & 16383;
    int bb = rem >> 9;
    int hh = rem & 511;
    out2[idx] = g_h[(size_t)l * (HDIM * BSZ) + (size_t)hh * BSZ + bb];
}

// ---------------- launch -----------------------------------------------------
extern "C" void kernel_launch(void* const* d_in, const int* in_sizes, int n_in,
                              void* d_out, int out_size) {
    const float* x    = (const float*)d_in[0];
    const float* Wih  = (const float*)d_in[1];
    const float* bih  = (const float*)d_in[2];
    const float* gih  = (const float*)d_in[3];
    const float* beih = (const float*)d_in[4];
    const float* Whh  = (const float*)d_in[5];
    const float* bhh  = (const float*)d_in[6];
    const float* ghh  = (const float*)d_in[7];
    const float* behh = (const float*)d_in[8];
    const float* Who  = (const float*)d_in[9];
    const float* bho  = (const float*)d_in[10];
    float* out = (float*)d_out;

    cudaFuncSetAttribute(k_recur, cudaFuncAttributeMaxDynamicSharedMemorySize, SMEM_RECUR);
    cudaFuncSetAttribute(k_gemm_zi_mma, cudaFuncAttributeMaxDynamicSharedMemorySize, ZI_SMEM);
    cudaFuncSetAttribute(k_gemm_out_mma, cudaFuncAttributeMaxDynamicSharedMemorySize, ZI_SMEM);

    k_init<<<64, 256>>>();
    {   // W_ih split
        __nv_bfloat16 *dhi, *dlo;
        cudaGetSymbolAddress((void**)&dhi, g_Whi);
        cudaGetSymbolAddress((void**)&dlo, g_Wlo);
        int n4 = LNUM * HDIM * DDIM / 4;
        k_cvt_split<<<(n4 + 255) / 256, 256>>>(Wih, dhi, dlo, n4);
    }
    {   // W_ho split
        __nv_bfloat16 *dhi, *dlo;
        cudaGetSymbolAddress((void**)&dhi, g_WOhi);
        cudaGetSymbolAddress((void**)&dlo, g_WOlo);
        int n4 = DDIM * HDIM / 4;
        k_cvt_split<<<(n4 + 255) / 256, 256>>>(Who, dhi, dlo, n4);
    }
    k_cvt_x<<<(TSTEPS * BSZ * DDIM / 4 + 255) / 256, 256>>>(x);
    k_gemm_zi_mma<<<dim3(16, 512), 512, ZI_SMEM>>>(bih);
    k_ln<<<LNUM * TSTEPS, 256>>>(gih, beih);
    k_recur<<<NCTA, 256, SMEM_RECUR>>>(Whh, bhh, ghh, behh);
    k_gemm_out_mma<<<dim3(4, 512), 512, ZI_SMEM>>>(bho, x, out);
    k_hfinal<<<256, 256>>>(out + (size_t)BSZ * TSTEPS * DDIM);
}